// round 2
// baseline (speedup 1.0000x reference)
#include <cuda_runtime.h>
#include <math.h>
#include <stdint.h>

#define NN 4096
#define DD 64
#define OMA 0.8f   // 1 - alpha(0.2)

// ---------------- scratch (device globals; allocation-free) ----------------
__device__ float g_W[(size_t)NN * NN];       // attention weights (unnormalized exp)
__device__ float g_h[NN * DD];               // per-GAT transformed features
__device__ float g_cat[NN * 4 * DD];         // concatenated heads [4096,256]
__device__ float g_x1[NN * DD];              // per-cell GAT output / next prev
__device__ float g_tb[NN * DD];              // x @ x1
__device__ float g_h1[NN * DD];              // relu(adj @ tb)
__device__ float g_u[NN * 32];               // h1 @ l2_w
__device__ float g_part[4 * NN * DD];        // split-K partials
__device__ float g_f1[NN], g_f2[NN], g_f1s[NN], g_rinv[NN];
__device__ int   g_pi[NN], g_tj[NN];

// ---------------- small matmul: C[4096,NC] = A[4096,K] @ B[K,NC] ----------------
template<int K, int NC>
__global__ void mm_small(const float* __restrict__ A, const float* __restrict__ B,
                         float* __restrict__ C) {
    constexpr int ROWS = 256 / NC;           // 4 (NC=64) or 8 (NC=32)
    __shared__ float Bs[64 * NC];
    __shared__ float As[ROWS * 64];
    int tid = threadIdx.x;
    int col = tid % NC, rl = tid / NC;
    int row0 = blockIdx.x * ROWS;
    float acc = 0.f;
    for (int kc = 0; kc < K; kc += 64) {
        for (int e = tid; e < 64 * NC; e += 256)
            Bs[e] = B[(size_t)(kc + e / NC) * NC + (e % NC)];
        for (int e = tid; e < ROWS * 64; e += 256)
            As[e] = A[(size_t)(row0 + e / 64) * K + kc + (e % 64)];
        __syncthreads();
        #pragma unroll 16
        for (int k = 0; k < 64; k++)
            acc += As[rl * 64 + k] * Bs[k * NC + col];
        __syncthreads();
    }
    C[(size_t)(row0 + rl) * NC + col] = acc;
}

// ---------------- f1 = h@a[:64], f2 = h@a[64:] (warp per row) ----------------
__global__ void fvec(const float* __restrict__ h, const float* __restrict__ a,
                     float* __restrict__ f1, float* __restrict__ f2) {
    int row = blockIdx.x * 8 + threadIdx.y;
    int lane = threadIdx.x;
    float v1 = 0.f, v2 = 0.f;
    #pragma unroll
    for (int d = lane; d < 64; d += 32) {
        float hv = h[(size_t)row * 64 + d];
        v1 += hv * a[d];
        v2 += hv * a[64 + d];
    }
    #pragma unroll
    for (int o = 16; o; o >>= 1) {
        v1 += __shfl_down_sync(0xffffffffu, v1, o);
        v2 += __shfl_down_sync(0xffffffffu, v2, o);
    }
    if (lane == 0) { f1[row] = v1; f2[row] = v2; }
}

// ---------------- bitonic sort (ascending by key) of 4096, single block ----------------
__global__ void sortk(const float* __restrict__ f1, float* __restrict__ f1s,
                      int* __restrict__ piout) {
    __shared__ float k[NN];
    __shared__ int   id[NN];
    int tid = threadIdx.x;  // 1024
    for (int r = tid; r < NN; r += 1024) { k[r] = f1[r]; id[r] = r; }
    __syncthreads();
    for (int size = 2; size <= NN; size <<= 1) {
        for (int stride = size >> 1; stride > 0; stride >>= 1) {
            #pragma unroll
            for (int t = tid; t < NN / 2; t += 1024) {
                int i = 2 * t - (t & (stride - 1));
                int j = i + stride;
                bool asc = ((i & size) == 0);
                float ki = k[i], kj = k[j];
                bool sw = asc ? (ki > kj) : (ki < kj);
                if (sw) {
                    k[i] = kj; k[j] = ki;
                    int ti = id[i]; id[i] = id[j]; id[j] = ti;
                }
            }
            __syncthreads();
        }
    }
    for (int r = tid; r < NN; r += 1024) { f1s[r] = k[r]; piout[r] = id[r]; }
}

// ---------------- t_j = #{k : f1s[k] <= -f2_j} ----------------
__global__ void tvec(const float* __restrict__ f1s, const float* __restrict__ f2,
                     int* __restrict__ tj) {
    int j = blockIdx.x * 256 + threadIdx.x;
    float thr = -f2[j];
    int lo = 0, hi = NN;
    while (lo < hi) {
        int mid = (lo + hi) >> 1;
        if (f1s[mid] <= thr) lo = mid + 1; else hi = mid;
    }
    tj[j] = lo;
}

// ---------------- phase A: per-row scan + softmax weights ----------------
// S_ij = A1 + A0*f2_j - (1-a)*(Q(t_j) + f2_j*P(t_j)); W[i,:] = exp(S-m), rinv=1/sum
__global__ void phaseA(const float* __restrict__ adj, const int* __restrict__ pi,
                       const float* __restrict__ f1s, const float* __restrict__ f2,
                       const int* __restrict__ tj, float* __restrict__ Wg,
                       float* __restrict__ rinv) {
    extern __shared__ float sm[];
    float* arow = sm;             // 4096
    float* sP = sm + 4096;        // 4352 (padded stride-17 chunks of 16)
    float* sQ = sP + 4352;        // 4352
    __shared__ float wsp[8], wsq[8];

    int i = blockIdx.x, tid = threadIdx.x;
    const float* Arow = adj + (size_t)i * NN;
    for (int r = tid; r < NN; r += 256) arow[r] = Arow[r];
    __syncthreads();
    for (int r = tid; r < NN; r += 256) {
        float a = arow[pi[r]];
        int pr = ((r >> 4) * 17) + (r & 15);
        sP[pr] = a;
        sQ[pr] = a * f1s[r];
    }
    __syncthreads();
    // serial scan of this thread's 16-chunk
    int base = tid * 17;
    float p = 0.f, q = 0.f;
    #pragma unroll
    for (int u = 0; u < 16; u++) {
        p += sP[base + u]; sP[base + u] = p;
        q += sQ[base + u]; sQ[base + u] = q;
    }
    // block scan of chunk totals
    float ip = p, iq = q;
    unsigned lane = tid & 31, wid = tid >> 5;
    #pragma unroll
    for (int o = 1; o < 32; o <<= 1) {
        float tp = __shfl_up_sync(0xffffffffu, ip, o);
        float tq = __shfl_up_sync(0xffffffffu, iq, o);
        if (lane >= o) { ip += tp; iq += tq; }
    }
    if (lane == 31) { wsp[wid] = ip; wsq[wid] = iq; }
    __syncthreads();
    float offp = 0.f, offq = 0.f;
    for (int w = 0; w < 8; w++)
        if (w < (int)wid) { offp += wsp[w]; offq += wsq[w]; }
    float ep = offp + ip - p;
    float eq = offq + iq - q;
    #pragma unroll
    for (int u = 0; u < 16; u++) { sP[base + u] += ep; sQ[base + u] += eq; }
    __syncthreads();
    float A0 = sP[255 * 17 + 15];
    float A1 = sQ[255 * 17 + 15];

    // pass 1: row max
    float m = -3.0e38f;
    for (int j = tid; j < NN; j += 256) {
        float f2j = f2[j];
        int t = tj[j];
        float Pt = 0.f, Qt = 0.f;
        if (t > 0) {
            int pidx = (((t - 1) >> 4) * 17) + ((t - 1) & 15);
            Pt = sP[pidx]; Qt = sQ[pidx];
        }
        float S = A1 + A0 * f2j - OMA * (Qt + f2j * Pt);
        m = fmaxf(m, S);
    }
    #pragma unroll
    for (int o = 16; o; o >>= 1) m = fmaxf(m, __shfl_xor_sync(0xffffffffu, m, o));
    __syncthreads();
    if (lane == 0) wsp[wid] = m;
    __syncthreads();
    float mall = wsp[0];
    #pragma unroll
    for (int w = 1; w < 8; w++) mall = fmaxf(mall, wsp[w]);

    // pass 2: exp + sum + write
    float z = 0.f;
    float* Wrow = Wg + (size_t)i * NN;
    for (int j = tid; j < NN; j += 256) {
        float f2j = f2[j];
        int t = tj[j];
        float Pt = 0.f, Qt = 0.f;
        if (t > 0) {
            int pidx = (((t - 1) >> 4) * 17) + ((t - 1) & 15);
            Pt = sP[pidx]; Qt = sQ[pidx];
        }
        float S = A1 + A0 * f2j - OMA * (Qt + f2j * Pt);
        float w = __expf(S - mall);
        z += w;
        Wrow[j] = w;
    }
    #pragma unroll
    for (int o = 16; o; o >>= 1) z += __shfl_xor_sync(0xffffffffu, z, o);
    __syncthreads();
    if (lane == 0) wsq[wid] = z;
    __syncthreads();
    if (tid == 0) {
        float zt = 0.f;
        #pragma unroll
        for (int w = 0; w < 8; w++) zt += wsq[w];
        rinv[i] = 1.0f / zt;
    }
}

// ---------------- big matmul: Cpart[split] = A[4096,4096-slice] @ B[4096,TN] ----------------
template<int TN>
__global__ void mm_big(const float* __restrict__ A, const float* __restrict__ B,
                       float* __restrict__ Cpart) {
    constexpr int TM = (TN == 64) ? 64 : 128;
    constexpr int THR_N = TN / 4;
    __shared__ float As[TM][33];
    __shared__ float Bs[32][TN];
    int m0 = blockIdx.x * TM;
    int klen = NN / gridDim.y;
    int kbeg = blockIdx.y * klen;
    int tid = threadIdx.x;
    int tx = tid % THR_N, ty = tid / THR_N;
    float acc[4][4] = {};
    for (int k0 = kbeg; k0 < kbeg + klen; k0 += 32) {
        #pragma unroll
        for (int e = tid; e < TM * 32; e += 256) {
            int r = e >> 5, k = e & 31;
            As[r][k] = A[(size_t)(m0 + r) * NN + k0 + k];
        }
        #pragma unroll
        for (int e = tid; e < 32 * TN; e += 256) {
            int k = e / TN, n = e % TN;
            Bs[k][n] = B[(size_t)(k0 + k) * TN + n];
        }
        __syncthreads();
        #pragma unroll
        for (int k = 0; k < 32; k++) {
            float b0 = Bs[k][tx * 4 + 0];
            float b1 = Bs[k][tx * 4 + 1];
            float b2 = Bs[k][tx * 4 + 2];
            float b3 = Bs[k][tx * 4 + 3];
            #pragma unroll
            for (int r = 0; r < 4; r++) {
                float a = As[ty * 4 + r][k];
                acc[r][0] += a * b0;
                acc[r][1] += a * b1;
                acc[r][2] += a * b2;
                acc[r][3] += a * b3;
            }
        }
        __syncthreads();
    }
    float* Cp = Cpart + (size_t)blockIdx.y * (NN * TN);
    #pragma unroll
    for (int r = 0; r < 4; r++) {
        int row = m0 + ty * 4 + r;
        float4 v = make_float4(acc[r][0], acc[r][1], acc[r][2], acc[r][3]);
        *(float4*)&Cp[(size_t)row * TN + tx * 4] = v;
    }
}

// ---------------- epilogue: combine split-K, scale, activation, strided store ----------------
// mode: 0 none, 1 relu, 2 elu
__global__ void epilogue_k(const float* __restrict__ part, int splits, int TN,
                           const float* __restrict__ rinv, float* __restrict__ dst,
                           int ldc, int mode) {
    int idx = blockIdx.x * 256 + threadIdx.x;
    int row = idx / TN, col = idx % TN;
    float v = 0.f;
    for (int s = 0; s < splits; s++) v += part[(size_t)s * NN * TN + idx];
    if (rinv) v *= rinv[row];
    if (mode == 1) v = fmaxf(v, 0.f);
    else if (mode == 2) v = (v > 0.f) ? v : expm1f(v);
    dst[(size_t)row * ldc + col] = v;
}

// ---------------- host orchestration ----------------
struct Bufs {
    float *W, *h, *cat, *x1, *tb, *h1, *u, *part, *f1, *f2, *f1s, *rinv;
    int *pi, *tj;
};

static void run_gat(const float* adjc, const float* F, int Kf,
                    const float* Hm, const float* av,
                    float* dst, int ldc, const Bufs& b) {
    if (Kf == 64) mm_small<64, 64><<<NN / 4, 256>>>(F, Hm, b.h);
    else          mm_small<256, 64><<<NN / 4, 256>>>(F, Hm, b.h);
    fvec<<<NN / 8, dim3(32, 8)>>>(b.h, av, b.f1, b.f2);
    sortk<<<1, 1024>>>(b.f1, b.f1s, b.pi);
    tvec<<<NN / 256, 256>>>(b.f1s, b.f2, b.tj);
    phaseA<<<NN, 256, (4096 + 4352 + 4352) * sizeof(float)>>>(
        adjc, b.pi, b.f1s, b.f2, b.tj, b.W, b.rinv);
    mm_big<64><<<dim3(NN / 64, 2), 256>>>(b.W, b.h, b.part);
    epilogue_k<<<NN * 64 / 256, 256>>>(b.part, 2, 64, b.rinv, dst, ldc, 2 /*elu*/);
}

extern "C" void kernel_launch(void* const* d_in, const int* in_sizes, int n_in,
                              void* d_out, int out_size) {
    const float* x      = (const float*)d_in[0];   // [2,4096,4096]
    const float* adj    = (const float*)d_in[1];   // [2,4096,4096]
    const float* w_init = (const float*)d_in[2];   // [4096,64]
    const float* head_H = (const float*)d_in[3];   // [2,4,64,64]
    const float* head_a = (const float*)d_in[4];   // [2,4,128,1]
    const float* out_H  = (const float*)d_in[5];   // [2,256,64]
    const float* out_a  = (const float*)d_in[6];   // [2,128,1]
    const float* l2_w   = (const float*)d_in[7];   // [2,64,32]
    float* out = (float*)d_out;                    // [4096,32]

    cudaFuncSetAttribute(phaseA, cudaFuncAttributeMaxDynamicSharedMemorySize,
                         (4096 + 4352 + 4352) * (int)sizeof(float));

    Bufs b;
    cudaGetSymbolAddress((void**)&b.W, g_W);
    cudaGetSymbolAddress((void**)&b.h, g_h);
    cudaGetSymbolAddress((void**)&b.cat, g_cat);
    cudaGetSymbolAddress((void**)&b.x1, g_x1);
    cudaGetSymbolAddress((void**)&b.tb, g_tb);
    cudaGetSymbolAddress((void**)&b.h1, g_h1);
    cudaGetSymbolAddress((void**)&b.u, g_u);
    cudaGetSymbolAddress((void**)&b.part, g_part);
    cudaGetSymbolAddress((void**)&b.f1, g_f1);
    cudaGetSymbolAddress((void**)&b.f2, g_f2);
    cudaGetSymbolAddress((void**)&b.f1s, g_f1s);
    cudaGetSymbolAddress((void**)&b.rinv, g_rinv);
    cudaGetSymbolAddress((void**)&b.pi, g_pi);
    cudaGetSymbolAddress((void**)&b.tj, g_tj);

    const float* prev = w_init;  // [4096,64]
    for (int i = 0; i < 2; i++) {
        const float* adjc = adj + (size_t)i * NN * NN;
        // 4 heads -> cat[:, g*64:(g+1)*64] (elu inside)
        for (int g = 0; g < 4; g++) {
            const float* Hm = head_H + (size_t)(i * 4 + g) * 64 * 64;
            const float* av = head_a + (size_t)(i * 4 + g) * 128;
            run_gat(adjc, prev, 64, Hm, av, b.cat + g * 64, 256, b);
        }
        // out-attention GAT: x1 = elu(att @ (cat @ out_H))
        run_gat(adjc, b.cat, 256, out_H + (size_t)i * 256 * 64,
                out_a + (size_t)i * 128, b.x1, 64, b);
        prev = b.x1;

        if (i == 1) {  // tail only matters for the last cell
            const float* xc = x + (size_t)i * NN * NN;
            // tb = x @ x1
            mm_big<64><<<dim3(NN / 64, 2), 256>>>(xc, b.x1, b.part);
            epilogue_k<<<NN * 64 / 256, 256>>>(b.part, 2, 64, nullptr, b.tb, 64, 0);
            // h1 = relu(adj @ tb)
            mm_big<64><<<dim3(NN / 64, 2), 256>>>(adjc, b.tb, b.part);
            epilogue_k<<<NN * 64 / 256, 256>>>(b.part, 2, 64, nullptr, b.h1, 64, 1);
            // u = h1 @ l2_w
            mm_small<64, 32><<<NN / 8, 256>>>(b.h1, l2_w + (size_t)i * 64 * 32, b.u);
            // out = adj @ u
            mm_big<32><<<dim3(NN / 128, 4), 256>>>(adjc, b.u, b.part);
            epilogue_k<<<NN * 32 / 256, 256>>>(b.part, 4, 32, nullptr, out, 32, 0);
        }
    }
}

// round 4
// speedup vs baseline: 1.8254x; 1.8254x over previous
#include <cuda_runtime.h>
#include <cuda_bf16.h>
#include <math.h>
#include <stdint.h>

#define NN 4096
#define DD 64
#define OMA 0.8f   // 1 - alpha(0.2)

// ---------------- scratch (device globals; allocation-free) ----------------
__device__ __nv_bfloat16 g_Whi[(size_t)NN * NN];
__device__ __nv_bfloat16 g_Wlo[(size_t)NN * NN];
__device__ __nv_bfloat16 g_ahi[(size_t)NN * NN];
__device__ __nv_bfloat16 g_alo[(size_t)NN * NN];
__device__ __nv_bfloat16 g_xhi[(size_t)NN * NN];
__device__ __nv_bfloat16 g_xlo[(size_t)NN * NN];
__device__ __nv_bfloat16 g_bhi[64 * NN];
__device__ __nv_bfloat16 g_blo[64 * NN];
__device__ float g_h[NN * DD];
__device__ float g_cat[NN * 4 * DD];
__device__ float g_x1[NN * DD];
__device__ float g_tb[NN * DD];
__device__ float g_h1[NN * DD];
__device__ float g_u[NN * 32];
__device__ float g_part[4 * NN * DD];
__device__ float g_f1[NN], g_f2[NN], g_f1s[NN], g_rinv[NN];
__device__ int   g_pi[NN], g_tj[NN];

// ================= portable (sm_80+) PTX helpers =================
__device__ __forceinline__ uint32_t smem_u32(const void* p) {
    uint32_t a;
    asm("{ .reg .u64 t; cvta.to.shared.u64 t, %1; cvt.u32.u64 %0, t; }"
        : "=r"(a) : "l"(p));
    return a;
}

#define CP16(dst, src) \
    asm volatile("cp.async.cg.shared.global [%0], [%1], 16;" :: "r"(dst), "l"(src))
#define CP_COMMIT() asm volatile("cp.async.commit_group;" ::: "memory")
#define CP_WAIT0() asm volatile("cp.async.wait_group 0;" ::: "memory")
#define CP_WAIT1() asm volatile("cp.async.wait_group 1;" ::: "memory")

__device__ __forceinline__ void ldm4(uint32_t* r, uint32_t addr) {
    asm volatile("ldmatrix.sync.aligned.m8n8.x4.shared.b16 {%0,%1,%2,%3}, [%4];"
        : "=r"(r[0]), "=r"(r[1]), "=r"(r[2]), "=r"(r[3]) : "r"(addr));
}

__device__ __forceinline__ void mma16816(float* d, const uint32_t* a, const uint32_t* b) {
    asm volatile("mma.sync.aligned.m16n8k16.row.col.f32.bf16.bf16.f32 "
        "{%0,%1,%2,%3}, {%4,%5,%6,%7}, {%8,%9}, {%0,%1,%2,%3};"
        : "+f"(d[0]), "+f"(d[1]), "+f"(d[2]), "+f"(d[3])
        : "r"(a[0]), "r"(a[1]), "r"(a[2]), "r"(a[3]), "r"(b[0]), "r"(b[1]));
}

__device__ __forceinline__ uint32_t swz(uint32_t bo) { return bo ^ ((bo >> 3) & 0x70); }

// ================= tensor-core big matmul (mma.sync bf16 pair-split) =================
// part[by][4096,64] = A[4096, k-slice] @ B^T ;  A planes row-major (K contig),
// B planes stored [64 n][4096 k] (K contig). 3 combos: AhBh + AhBl + AlBh.
#define O_AH 0
#define O_AL 16384
#define O_BH 32768
#define O_BL 40960
#define STG  49152
#define MMSMEM (2 * STG)

__global__ void __launch_bounds__(256, 1) mm_mma(
        const __nv_bfloat16* __restrict__ Ahi, const __nv_bfloat16* __restrict__ Alo,
        const __nv_bfloat16* __restrict__ Bhi, const __nv_bfloat16* __restrict__ Blo,
        float* __restrict__ part) {
    extern __shared__ char smem[];
    uint32_t sb = smem_u32(smem);
    int tid = threadIdx.x, wid = tid >> 5, lane = tid & 31;
    int m0 = blockIdx.x * 128;
    int klen = NN / gridDim.y;
    int kbeg = blockIdx.y * klen;
    int nch = klen / 64;
    int wm = wid >> 1, wn = wid & 1;

    auto load_chunk = [&](int ch) {
        uint32_t base = sb + (uint32_t)(ch & 1) * STG;
        int kc = kbeg + ch * 64;
        int r = tid >> 3, c = tid & 7;
        uint32_t sw = swz((uint32_t)(r * 128 + c * 16));
        #pragma unroll
        for (int pl = 0; pl < 2; pl++) {
            const __nv_bfloat16* src = pl ? Alo : Ahi;
            uint32_t off = pl ? O_AL : O_AH;
            #pragma unroll
            for (int i = 0; i < 4; i++)   // 128 rows, 32 rows per iter
                CP16(base + off + sw + (uint32_t)i * 4096,
                     src + (size_t)(m0 + r + i * 32) * NN + kc + c * 8);
        }
        #pragma unroll
        for (int pl = 0; pl < 2; pl++) {
            const __nv_bfloat16* src = pl ? Blo : Bhi;
            uint32_t off = pl ? O_BL : O_BH;
            #pragma unroll
            for (int i = 0; i < 2; i++)   // 64 rows
                CP16(base + off + sw + (uint32_t)i * 4096,
                     src + (size_t)(r + i * 32) * NN + kc + c * 8);
        }
        CP_COMMIT();
    };

    float acc[2][4][4] = {};

    load_chunk(0);
    for (int ch = 0; ch < nch; ch++) {
        if (ch + 1 < nch) { load_chunk(ch + 1); CP_WAIT1(); }
        else               { CP_WAIT0(); }
        __syncthreads();
        uint32_t base = sb + (uint32_t)(ch & 1) * STG;
        #pragma unroll
        for (int ks = 0; ks < 4; ks++) {
            uint32_t ah[2][4], al[2][4], bh[8], bl[8];
            // A fragments (m16k16 per m-tile)
            #pragma unroll
            for (int mt = 0; mt < 2; mt++) {
                int row = wm * 32 + mt * 16 + (lane & 7) + ((lane >> 3) & 1) * 8;
                int koff = ks * 32 + (lane >> 4) * 16;
                uint32_t sw = swz((uint32_t)(row * 128 + koff));
                ldm4(ah[mt], base + O_AH + sw);
                ldm4(al[mt], base + O_AL + sw);
            }
            // B fragments: two ldmatrix.x4 per plane cover 4 n8k16 tiles
            #pragma unroll
            for (int half = 0; half < 2; half++) {
                int g = lane >> 3;
                int n = wn * 32 + half * 16 + (g >> 1) * 8 + (lane & 7);
                int koff = ks * 32 + (g & 1) * 16;
                uint32_t sw = swz((uint32_t)(n * 128 + koff));
                ldm4(bh + half * 4, base + O_BH + sw);
                ldm4(bl + half * 4, base + O_BL + sw);
            }
            #pragma unroll
            for (int mt = 0; mt < 2; mt++)
                #pragma unroll
                for (int nt = 0; nt < 4; nt++) {
                    mma16816(acc[mt][nt], ah[mt], bh + nt * 2);
                    mma16816(acc[mt][nt], ah[mt], bl + nt * 2);
                    mma16816(acc[mt][nt], al[mt], bh + nt * 2);
                }
        }
        __syncthreads();
    }

    float* cp = part + (size_t)blockIdx.y * (NN * 64);
    #pragma unroll
    for (int mt = 0; mt < 2; mt++)
        #pragma unroll
        for (int nt = 0; nt < 4; nt++) {
            int row = m0 + wm * 32 + mt * 16 + (lane >> 2);
            int col = wn * 32 + nt * 8 + (lane & 3) * 2;
            *(float2*)&cp[(size_t)row * 64 + col] =
                make_float2(acc[mt][nt][0], acc[mt][nt][1]);
            *(float2*)&cp[(size_t)(row + 8) * 64 + col] =
                make_float2(acc[mt][nt][2], acc[mt][nt][3]);
        }
}

// ---------------- fp32 -> bf16 pair planes (big matrices) ----------------
__global__ void cpair(const float4* __restrict__ in, __nv_bfloat16* __restrict__ hi,
                      __nv_bfloat16* __restrict__ lo) {
    size_t n4 = (size_t)NN * NN / 4;
    for (size_t i = (size_t)blockIdx.x * 256 + threadIdx.x; i < n4;
         i += (size_t)gridDim.x * 256) {
        float4 v = in[i];
        __nv_bfloat16 h0 = __float2bfloat16_rn(v.x);
        __nv_bfloat16 h1 = __float2bfloat16_rn(v.y);
        __nv_bfloat16 h2 = __float2bfloat16_rn(v.z);
        __nv_bfloat16 h3 = __float2bfloat16_rn(v.w);
        __nv_bfloat162* H = (__nv_bfloat162*)hi;
        __nv_bfloat162* L = (__nv_bfloat162*)lo;
        H[2 * i]     = __nv_bfloat162(h0, h1);
        H[2 * i + 1] = __nv_bfloat162(h2, h3);
        L[2 * i]     = __nv_bfloat162(__float2bfloat16_rn(v.x - __bfloat162float(h0)),
                                      __float2bfloat16_rn(v.y - __bfloat162float(h1)));
        L[2 * i + 1] = __nv_bfloat162(__float2bfloat16_rn(v.z - __bfloat162float(h2)),
                                      __float2bfloat16_rn(v.w - __bfloat162float(h3)));
    }
}

// ---------------- transpose+convert: in [4096,C] fp32 -> out [64][4096] bf16 pair ----------------
__global__ void tconv(const float* __restrict__ in, int C,
                      __nv_bfloat16* __restrict__ ohi, __nv_bfloat16* __restrict__ olo) {
    __shared__ float t[32][33];
    int bx = blockIdx.x, by = blockIdx.y;
    int x = threadIdx.x, y = threadIdx.y;   // 32x8
    int col0 = by * 32;
    for (int yy = y; yy < 32; yy += 8) {
        int r = bx * 32 + yy, c = col0 + x;
        t[yy][x] = (c < C) ? in[(size_t)r * C + c] : 0.f;
    }
    __syncthreads();
    for (int yy = y; yy < 32; yy += 8) {
        int n = col0 + yy;
        int k = bx * 32 + x;
        float v = t[x][yy];
        __nv_bfloat16 h = __float2bfloat16_rn(v);
        ohi[(size_t)n * NN + k] = h;
        olo[(size_t)n * NN + k] = __float2bfloat16_rn(v - __bfloat162float(h));
    }
}

// ---------------- small matmul: C[4096,NC] = A[4096,K] @ B[K,NC] ----------------
template<int K, int NC>
__global__ void mm_small(const float* __restrict__ A, const float* __restrict__ B,
                         float* __restrict__ C) {
    constexpr int ROWS = 256 / NC;
    __shared__ float Bs[64 * NC];
    __shared__ float As[ROWS * 64];
    int tid = threadIdx.x;
    int col = tid % NC, rl = tid / NC;
    int row0 = blockIdx.x * ROWS;
    float acc = 0.f;
    for (int kc = 0; kc < K; kc += 64) {
        for (int e = tid; e < 64 * NC; e += 256)
            Bs[e] = B[(size_t)(kc + e / NC) * NC + (e % NC)];
        for (int e = tid; e < ROWS * 64; e += 256)
            As[e] = A[(size_t)(row0 + e / 64) * K + kc + (e % 64)];
        __syncthreads();
        #pragma unroll 16
        for (int k = 0; k < 64; k++)
            acc += As[rl * 64 + k] * Bs[k * NC + col];
        __syncthreads();
    }
    C[(size_t)(row0 + rl) * NC + col] = acc;
}

// ---------------- f1/f2 ----------------
__global__ void fvec(const float* __restrict__ h, const float* __restrict__ a,
                     float* __restrict__ f1, float* __restrict__ f2) {
    int row = blockIdx.x * 8 + threadIdx.y;
    int lane = threadIdx.x;
    float v1 = 0.f, v2 = 0.f;
    #pragma unroll
    for (int d = lane; d < 64; d += 32) {
        float hv = h[(size_t)row * 64 + d];
        v1 += hv * a[d];
        v2 += hv * a[64 + d];
    }
    #pragma unroll
    for (int o = 16; o; o >>= 1) {
        v1 += __shfl_down_sync(0xffffffffu, v1, o);
        v2 += __shfl_down_sync(0xffffffffu, v2, o);
    }
    if (lane == 0) { f1[row] = v1; f2[row] = v2; }
}

// ---------------- bitonic sort of 4096 keys ----------------
__global__ void sortk(const float* __restrict__ f1, float* __restrict__ f1s,
                      int* __restrict__ piout) {
    __shared__ float k[NN];
    __shared__ int   id[NN];
    int tid = threadIdx.x;
    for (int r = tid; r < NN; r += 1024) { k[r] = f1[r]; id[r] = r; }
    __syncthreads();
    for (int size = 2; size <= NN; size <<= 1) {
        for (int stride = size >> 1; stride > 0; stride >>= 1) {
            #pragma unroll
            for (int t = tid; t < NN / 2; t += 1024) {
                int i = 2 * t - (t & (stride - 1));
                int j = i + stride;
                bool asc = ((i & size) == 0);
                float ki = k[i], kj = k[j];
                bool sw = asc ? (ki > kj) : (ki < kj);
                if (sw) {
                    k[i] = kj; k[j] = ki;
                    int ti = id[i]; id[i] = id[j]; id[j] = ti;
                }
            }
            __syncthreads();
        }
    }
    for (int r = tid; r < NN; r += 1024) { f1s[r] = k[r]; piout[r] = id[r]; }
}

// ---------------- t_j = #{k : f1s[k] <= -f2_j} ----------------
__global__ void tvec(const float* __restrict__ f1s, const float* __restrict__ f2,
                     int* __restrict__ tj) {
    int j = blockIdx.x * 256 + threadIdx.x;
    float thr = -f2[j];
    int lo = 0, hi = NN;
    while (lo < hi) {
        int mid = (lo + hi) >> 1;
        if (f1s[mid] <= thr) lo = mid + 1; else hi = mid;
    }
    tj[j] = lo;
}

// ---------------- phase A: scans + softmax weights (bf16 pair output) ----------------
__global__ void phaseA(const float* __restrict__ adj, const int* __restrict__ pi,
                       const float* __restrict__ f1s, const float* __restrict__ f2,
                       const int* __restrict__ tj,
                       __nv_bfloat16* __restrict__ Whi, __nv_bfloat16* __restrict__ Wlo,
                       float* __restrict__ rinv) {
    extern __shared__ float sm[];
    float* arow = sm;
    float* sP = sm + 4096;
    float* sQ = sP + 4352;
    __shared__ float wsp[8], wsq[8];

    int i = blockIdx.x, tid = threadIdx.x;
    const float* Arow = adj + (size_t)i * NN;
    for (int r = tid; r < NN; r += 256) arow[r] = Arow[r];
    __syncthreads();
    for (int r = tid; r < NN; r += 256) {
        float a = arow[pi[r]];
        int pr = ((r >> 4) * 17) + (r & 15);
        sP[pr] = a;
        sQ[pr] = a * f1s[r];
    }
    __syncthreads();
    int base = tid * 17;
    float p = 0.f, q = 0.f;
    #pragma unroll
    for (int u = 0; u < 16; u++) {
        p += sP[base + u]; sP[base + u] = p;
        q += sQ[base + u]; sQ[base + u] = q;
    }
    float ip = p, iq = q;
    unsigned lane = tid & 31, wid = tid >> 5;
    #pragma unroll
    for (int o = 1; o < 32; o <<= 1) {
        float tp = __shfl_up_sync(0xffffffffu, ip, o);
        float tq = __shfl_up_sync(0xffffffffu, iq, o);
        if (lane >= o) { ip += tp; iq += tq; }
    }
    if (lane == 31) { wsp[wid] = ip; wsq[wid] = iq; }
    __syncthreads();
    float offp = 0.f, offq = 0.f;
    for (int w = 0; w < 8; w++)
        if (w < (int)wid) { offp += wsp[w]; offq += wsq[w]; }
    float ep = offp + ip - p;
    float eq = offq + iq - q;
    #pragma unroll
    for (int u = 0; u < 16; u++) { sP[base + u] += ep; sQ[base + u] += eq; }
    __syncthreads();
    float A0 = sP[255 * 17 + 15];
    float A1 = sQ[255 * 17 + 15];

    float m = -3.0e38f;
    for (int j = tid; j < NN; j += 256) {
        float f2j = f2[j];
        int t = tj[j];
        float Pt = 0.f, Qt = 0.f;
        if (t > 0) {
            int pidx = (((t - 1) >> 4) * 17) + ((t - 1) & 15);
            Pt = sP[pidx]; Qt = sQ[pidx];
        }
        float S = A1 + A0 * f2j - OMA * (Qt + f2j * Pt);
        m = fmaxf(m, S);
    }
    #pragma unroll
    for (int o = 16; o; o >>= 1) m = fmaxf(m, __shfl_xor_sync(0xffffffffu, m, o));
    __syncthreads();
    if (lane == 0) wsp[wid] = m;
    __syncthreads();
    float mall = wsp[0];
    #pragma unroll
    for (int w = 1; w < 8; w++) mall = fmaxf(mall, wsp[w]);

    float z = 0.f;
    __nv_bfloat16* Wh = Whi + (size_t)i * NN;
    __nv_bfloat16* Wl = Wlo + (size_t)i * NN;
    for (int j = tid; j < NN; j += 256) {
        float f2j = f2[j];
        int t = tj[j];
        float Pt = 0.f, Qt = 0.f;
        if (t > 0) {
            int pidx = (((t - 1) >> 4) * 17) + ((t - 1) & 15);
            Pt = sP[pidx]; Qt = sQ[pidx];
        }
        float S = A1 + A0 * f2j - OMA * (Qt + f2j * Pt);
        float w = __expf(S - mall);
        z += w;
        __nv_bfloat16 hb = __float2bfloat16_rn(w);
        Wh[j] = hb;
        Wl[j] = __float2bfloat16_rn(w - __bfloat162float(hb));
    }
    #pragma unroll
    for (int o = 16; o; o >>= 1) z += __shfl_xor_sync(0xffffffffu, z, o);
    __syncthreads();
    if (lane == 0) wsq[wid] = z;
    __syncthreads();
    if (tid == 0) {
        float zt = 0.f;
        #pragma unroll
        for (int w = 0; w < 8; w++) zt += wsq[w];
        rinv[i] = 1.0f / zt;
    }
}

// ---------------- epilogues ----------------
__global__ void epilogue_k(const float* __restrict__ part, int splits,
                           const float* __restrict__ rinv, float* __restrict__ dst,
                           int ldc, int mode) {
    int idx = blockIdx.x * 256 + threadIdx.x;
    int row = idx >> 6, col = idx & 63;
    float v = 0.f;
    for (int s = 0; s < splits; s++) v += part[(size_t)s * NN * 64 + idx];
    if (rinv) v *= rinv[row];
    if (mode == 1) v = fmaxf(v, 0.f);
    else if (mode == 2) v = (v > 0.f) ? v : expm1f(v);
    dst[(size_t)row * ldc + col] = v;
}

__global__ void epi32(const float* __restrict__ part, float* __restrict__ dst) {
    int idx = blockIdx.x * 256 + threadIdx.x;
    int row = idx >> 5, col = idx & 31;
    float v = 0.f;
    for (int s = 0; s < 4; s++) v += part[(size_t)s * NN * 64 + (size_t)row * 64 + col];
    dst[idx] = v;
}

// ---------------- host orchestration ----------------
struct Bufs {
    __nv_bfloat16 *Whi, *Wlo, *ahi, *alo, *xhi, *xlo, *bhi, *blo;
    float *h, *cat, *x1, *tb, *h1, *u, *part, *f1, *f2, *f1s, *rinv;
    int *pi, *tj;
};

static void run_gat(const float* adjc, const float* F, int Kf,
                    const float* Hm, const float* av,
                    float* dst, int ldc, const Bufs& b) {
    if (Kf == 64) mm_small<64, 64><<<NN / 4, 256>>>(F, Hm, b.h);
    else          mm_small<256, 64><<<NN / 4, 256>>>(F, Hm, b.h);
    fvec<<<NN / 8, dim3(32, 8)>>>(b.h, av, b.f1, b.f2);
    tconv<<<dim3(128, 2), dim3(32, 8)>>>(b.h, 64, b.bhi, b.blo);
    sortk<<<1, 1024>>>(b.f1, b.f1s, b.pi);
    tvec<<<NN / 256, 256>>>(b.f1s, b.f2, b.tj);
    phaseA<<<NN, 256, (4096 + 4352 + 4352) * sizeof(float)>>>(
        adjc, b.pi, b.f1s, b.f2, b.tj, b.Whi, b.Wlo, b.rinv);
    mm_mma<<<dim3(32, 4), 256, MMSMEM>>>(b.Whi, b.Wlo, b.bhi, b.blo, b.part);
    epilogue_k<<<NN * 64 / 256, 256>>>(b.part, 4, b.rinv, dst, ldc, 2 /*elu*/);
}

extern "C" void kernel_launch(void* const* d_in, const int* in_sizes, int n_in,
                              void* d_out, int out_size) {
    const float* x      = (const float*)d_in[0];
    const float* adj    = (const float*)d_in[1];
    const float* w_init = (const float*)d_in[2];
    const float* head_H = (const float*)d_in[3];
    const float* head_a = (const float*)d_in[4];
    const float* out_H  = (const float*)d_in[5];
    const float* out_a  = (const float*)d_in[6];
    const float* l2_w   = (const float*)d_in[7];
    float* out = (float*)d_out;

    cudaFuncSetAttribute(phaseA, cudaFuncAttributeMaxDynamicSharedMemorySize,
                         (4096 + 4352 + 4352) * (int)sizeof(float));
    cudaFuncSetAttribute(mm_mma, cudaFuncAttributeMaxDynamicSharedMemorySize, MMSMEM);

    Bufs b;
    cudaGetSymbolAddress((void**)&b.Whi, g_Whi);
    cudaGetSymbolAddress((void**)&b.Wlo, g_Wlo);
    cudaGetSymbolAddress((void**)&b.ahi, g_ahi);
    cudaGetSymbolAddress((void**)&b.alo, g_alo);
    cudaGetSymbolAddress((void**)&b.xhi, g_xhi);
    cudaGetSymbolAddress((void**)&b.xlo, g_xlo);
    cudaGetSymbolAddress((void**)&b.bhi, g_bhi);
    cudaGetSymbolAddress((void**)&b.blo, g_blo);
    cudaGetSymbolAddress((void**)&b.h, g_h);
    cudaGetSymbolAddress((void**)&b.cat, g_cat);
    cudaGetSymbolAddress((void**)&b.x1, g_x1);
    cudaGetSymbolAddress((void**)&b.tb, g_tb);
    cudaGetSymbolAddress((void**)&b.h1, g_h1);
    cudaGetSymbolAddress((void**)&b.u, g_u);
    cudaGetSymbolAddress((void**)&b.part, g_part);
    cudaGetSymbolAddress((void**)&b.f1, g_f1);
    cudaGetSymbolAddress((void**)&b.f2, g_f2);
    cudaGetSymbolAddress((void**)&b.f1s, g_f1s);
    cudaGetSymbolAddress((void**)&b.rinv, g_rinv);
    cudaGetSymbolAddress((void**)&b.pi, g_pi);
    cudaGetSymbolAddress((void**)&b.tj, g_tj);

    const float* prev = w_init;
    for (int i = 0; i < 2; i++) {
        const float* adjc = adj + (size_t)i * NN * NN;
        for (int g = 0; g < 4; g++) {
            const float* Hm = head_H + (size_t)(i * 4 + g) * 64 * 64;
            const float* av = head_a + (size_t)(i * 4 + g) * 128;
            run_gat(adjc, prev, 64, Hm, av, b.cat + g * 64, 256, b);
        }
        run_gat(adjc, b.cat, 256, out_H + (size_t)i * 256 * 64,
                out_a + (size_t)i * 128, b.x1, 64, b);
        prev = b.x1;

        if (i == 1) {
            const float* xc = x + (size_t)i * NN * NN;
            cpair<<<4096, 256>>>((const float4*)xc, b.xhi, b.xlo);
            cpair<<<4096, 256>>>((const float4*)adjc, b.ahi, b.alo);
            // tb = x @ x1
            tconv<<<dim3(128, 2), dim3(32, 8)>>>(b.x1, 64, b.bhi, b.blo);
            mm_mma<<<dim3(32, 4), 256, MMSMEM>>>(b.xhi, b.xlo, b.bhi, b.blo, b.part);
            epilogue_k<<<NN * 64 / 256, 256>>>(b.part, 4, nullptr, b.tb, 64, 0);
            // h1 = relu(adj @ tb)
            tconv<<<dim3(128, 2), dim3(32, 8)>>>(b.tb, 64, b.bhi, b.blo);
            mm_mma<<<dim3(32, 4), 256, MMSMEM>>>(b.ahi, b.alo, b.bhi, b.blo, b.part);
            epilogue_k<<<NN * 64 / 256, 256>>>(b.part, 4, nullptr, b.h1, 64, 1);
            // u = h1 @ l2_w
            mm_small<64, 32><<<NN / 8, 256>>>(b.h1, l2_w + (size_t)i * 64 * 32, b.u);
            // out = adj @ u   (u padded to 64 cols by tconv)
            tconv<<<dim3(128, 2), dim3(32, 8)>>>(b.u, 32, b.bhi, b.blo);
            mm_mma<<<dim3(32, 4), 256, MMSMEM>>>(b.ahi, b.alo, b.bhi, b.blo, b.part);
            epi32<<<NN * 32 / 256, 256>>>(b.part, out);
        }
    }
}

// round 5
// speedup vs baseline: 2.4039x; 1.3169x over previous
#include <cuda_runtime.h>
#include <cuda_bf16.h>
#include <math.h>
#include <stdint.h>

#define NN 4096
#define DD 64
#define OMA 0.8f   // 1 - alpha(0.2)
#define NH 4

// ---------------- scratch (device globals; allocation-free) ----------------
__device__ __nv_bfloat16 g_Whi[(size_t)NH * NN * NN];
__device__ __nv_bfloat16 g_Wlo[(size_t)NH * NN * NN];
__device__ __nv_bfloat16 g_ahi[(size_t)NN * NN];
__device__ __nv_bfloat16 g_alo[(size_t)NN * NN];
__device__ __nv_bfloat16 g_xhi[(size_t)NN * NN];
__device__ __nv_bfloat16 g_xlo[(size_t)NN * NN];
__device__ __nv_bfloat16 g_bhi[NH * 64 * NN];
__device__ __nv_bfloat16 g_blo[NH * 64 * NN];
__device__ float g_h[NH * NN * DD];
__device__ float g_cat[NN * NH * DD];
__device__ float g_x1[NN * DD];
__device__ float g_tb[NN * DD];
__device__ float g_h1[NN * DD];
__device__ float g_u[NN * 32];
__device__ float g_part[8 * NN * DD];              // 8 slabs (8 splits or 4 heads x 2)
__device__ float g_f1[NH * NN], g_f2[NH * NN], g_f1s[NH * NN], g_rinv[NH * NN];
__device__ int   g_pi[NH * NN], g_tj[NH * NN];

// ================= portable (sm_80+) PTX helpers =================
__device__ __forceinline__ uint32_t smem_u32(const void* p) {
    uint32_t a;
    asm("{ .reg .u64 t; cvta.to.shared.u64 t, %1; cvt.u32.u64 %0, t; }"
        : "=r"(a) : "l"(p));
    return a;
}

#define CP16(dst, src) \
    asm volatile("cp.async.cg.shared.global [%0], [%1], 16;" :: "r"(dst), "l"(src))
#define CP_COMMIT() asm volatile("cp.async.commit_group;" ::: "memory")
#define CP_WAIT0() asm volatile("cp.async.wait_group 0;" ::: "memory")
#define CP_WAIT1() asm volatile("cp.async.wait_group 1;" ::: "memory")

__device__ __forceinline__ void ldm4(uint32_t* r, uint32_t addr) {
    asm volatile("ldmatrix.sync.aligned.m8n8.x4.shared.b16 {%0,%1,%2,%3}, [%4];"
        : "=r"(r[0]), "=r"(r[1]), "=r"(r[2]), "=r"(r[3]) : "r"(addr));
}

__device__ __forceinline__ void mma16816(float* d, const uint32_t* a, const uint32_t* b) {
    asm volatile("mma.sync.aligned.m16n8k16.row.col.f32.bf16.bf16.f32 "
        "{%0,%1,%2,%3}, {%4,%5,%6,%7}, {%8,%9}, {%0,%1,%2,%3};"
        : "+f"(d[0]), "+f"(d[1]), "+f"(d[2]), "+f"(d[3])
        : "r"(a[0]), "r"(a[1]), "r"(a[2]), "r"(a[3]), "r"(b[0]), "r"(b[1]));
}

__device__ __forceinline__ uint32_t swz(uint32_t bo) { return bo ^ ((bo >> 3) & 0x70); }

// ================= tensor-core big matmul (mma.sync bf16 pair-split) =================
// slab[z*splits+y] = A_z[4096, k-slice(y)] @ B_z^T.  blockIdx.z selects head.
#define O_AH 0
#define O_AL 16384
#define O_BH 32768
#define O_BL 40960
#define STG  49152
#define MMSMEM (2 * STG)

__global__ void __launch_bounds__(256, 1) mm_mma(
        const __nv_bfloat16* __restrict__ Ahi, const __nv_bfloat16* __restrict__ Alo,
        const __nv_bfloat16* __restrict__ Bhi, const __nv_bfloat16* __restrict__ Blo,
        float* __restrict__ part, size_t aStr, size_t bStr) {
    extern __shared__ char smem[];
    uint32_t sb = smem_u32(smem);
    int tid = threadIdx.x, wid = tid >> 5, lane = tid & 31;
    int m0 = blockIdx.x * 128;
    int klen = NN / gridDim.y;
    int kbeg = blockIdx.y * klen;
    int nch = klen / 64;
    int wm = wid >> 1, wn = wid & 1;
    size_t zo = (size_t)blockIdx.z;
    const __nv_bfloat16* AhiZ = Ahi + zo * aStr;
    const __nv_bfloat16* AloZ = Alo + zo * aStr;
    const __nv_bfloat16* BhiZ = Bhi + zo * bStr;
    const __nv_bfloat16* BloZ = Blo + zo * bStr;

    auto load_chunk = [&](int ch) {
        uint32_t base = sb + (uint32_t)(ch & 1) * STG;
        int kc = kbeg + ch * 64;
        int r = tid >> 3, c = tid & 7;
        uint32_t sw = swz((uint32_t)(r * 128 + c * 16));
        #pragma unroll
        for (int pl = 0; pl < 2; pl++) {
            const __nv_bfloat16* src = pl ? AloZ : AhiZ;
            uint32_t off = pl ? O_AL : O_AH;
            #pragma unroll
            for (int i = 0; i < 4; i++)
                CP16(base + off + sw + (uint32_t)i * 4096,
                     src + (size_t)(m0 + r + i * 32) * NN + kc + c * 8);
        }
        #pragma unroll
        for (int pl = 0; pl < 2; pl++) {
            const __nv_bfloat16* src = pl ? BloZ : BhiZ;
            uint32_t off = pl ? O_BL : O_BH;
            #pragma unroll
            for (int i = 0; i < 2; i++)
                CP16(base + off + sw + (uint32_t)i * 4096,
                     src + (size_t)(r + i * 32) * NN + kc + c * 8);
        }
        CP_COMMIT();
    };

    float acc[2][4][4] = {};
    load_chunk(0);
    for (int ch = 0; ch < nch; ch++) {
        if (ch + 1 < nch) { load_chunk(ch + 1); CP_WAIT1(); }
        else               { CP_WAIT0(); }
        __syncthreads();
        uint32_t base = sb + (uint32_t)(ch & 1) * STG;
        #pragma unroll
        for (int ks = 0; ks < 4; ks++) {
            uint32_t ah[2][4], al[2][4], bh[8], bl[8];
            #pragma unroll
            for (int mt = 0; mt < 2; mt++) {
                int row = wm * 32 + mt * 16 + (lane & 7) + ((lane >> 3) & 1) * 8;
                int koff = ks * 32 + (lane >> 4) * 16;
                uint32_t sw = swz((uint32_t)(row * 128 + koff));
                ldm4(ah[mt], base + O_AH + sw);
                ldm4(al[mt], base + O_AL + sw);
            }
            #pragma unroll
            for (int half = 0; half < 2; half++) {
                int g = lane >> 3;
                int n = wn * 32 + half * 16 + (g >> 1) * 8 + (lane & 7);
                int koff = ks * 32 + (g & 1) * 16;
                uint32_t sw = swz((uint32_t)(n * 128 + koff));
                ldm4(bh + half * 4, base + O_BH + sw);
                ldm4(bl + half * 4, base + O_BL + sw);
            }
            #pragma unroll
            for (int mt = 0; mt < 2; mt++)
                #pragma unroll
                for (int nt = 0; nt < 4; nt++) {
                    mma16816(acc[mt][nt], ah[mt], bh + nt * 2);
                    mma16816(acc[mt][nt], ah[mt], bl + nt * 2);
                    mma16816(acc[mt][nt], al[mt], bh + nt * 2);
                }
        }
        __syncthreads();
    }

    float* cp = part + ((size_t)blockIdx.z * gridDim.y + blockIdx.y) * (NN * 64);
    #pragma unroll
    for (int mt = 0; mt < 2; mt++)
        #pragma unroll
        for (int nt = 0; nt < 4; nt++) {
            int row = m0 + wm * 32 + mt * 16 + (lane >> 2);
            int col = wn * 32 + nt * 8 + (lane & 3) * 2;
            *(float2*)&cp[(size_t)row * 64 + col] =
                make_float2(acc[mt][nt][0], acc[mt][nt][1]);
            *(float2*)&cp[(size_t)(row + 8) * 64 + col] =
                make_float2(acc[mt][nt][2], acc[mt][nt][3]);
        }
}

// ---------------- fp32 -> bf16 pair planes (big matrices) ----------------
__global__ void cpair(const float4* __restrict__ in, __nv_bfloat16* __restrict__ hi,
                      __nv_bfloat16* __restrict__ lo) {
    size_t n4 = (size_t)NN * NN / 4;
    for (size_t i = (size_t)blockIdx.x * 256 + threadIdx.x; i < n4;
         i += (size_t)gridDim.x * 256) {
        float4 v = in[i];
        __nv_bfloat16 h0 = __float2bfloat16_rn(v.x);
        __nv_bfloat16 h1 = __float2bfloat16_rn(v.y);
        __nv_bfloat16 h2 = __float2bfloat16_rn(v.z);
        __nv_bfloat16 h3 = __float2bfloat16_rn(v.w);
        __nv_bfloat162* H = (__nv_bfloat162*)hi;
        __nv_bfloat162* L = (__nv_bfloat162*)lo;
        H[2 * i]     = __nv_bfloat162(h0, h1);
        H[2 * i + 1] = __nv_bfloat162(h2, h3);
        L[2 * i]     = __nv_bfloat162(__float2bfloat16_rn(v.x - __bfloat162float(h0)),
                                      __float2bfloat16_rn(v.y - __bfloat162float(h1)));
        L[2 * i + 1] = __nv_bfloat162(__float2bfloat16_rn(v.z - __bfloat162float(h2)),
                                      __float2bfloat16_rn(v.w - __bfloat162float(h3)));
    }
}

// ---------------- transpose+convert: [4096,C] fp32 -> [64][4096] bf16 pair, per head z ----------------
__global__ void tconv(const float* __restrict__ in, int C,
                      __nv_bfloat16* __restrict__ ohi, __nv_bfloat16* __restrict__ olo) {
    __shared__ float t[32][33];
    size_t z = blockIdx.z;
    const float* inz = in + z * (size_t)NN * 64;
    __nv_bfloat16* oh = ohi + z * (size_t)64 * NN;
    __nv_bfloat16* ol = olo + z * (size_t)64 * NN;
    int bx = blockIdx.x, by = blockIdx.y;
    int x = threadIdx.x, y = threadIdx.y;   // 32x8
    int col0 = by * 32;
    for (int yy = y; yy < 32; yy += 8) {
        int r = bx * 32 + yy, c = col0 + x;
        t[yy][x] = (c < C) ? inz[(size_t)r * C + c] : 0.f;
    }
    __syncthreads();
    for (int yy = y; yy < 32; yy += 8) {
        int n = col0 + yy;
        int k = bx * 32 + x;
        float v = t[x][yy];
        __nv_bfloat16 h = __float2bfloat16_rn(v);
        oh[(size_t)n * NN + k] = h;
        ol[(size_t)n * NN + k] = __float2bfloat16_rn(v - __bfloat162float(h));
    }
}

// ---------------- small matmul: C[4096,NC] = A[4096,K] @ B[K,NC], head = blockIdx.y ----------------
template<int K, int NC>
__global__ void mm_small(const float* __restrict__ A, const float* __restrict__ B,
                         float* __restrict__ C) {
    constexpr int ROWS = 256 / NC;
    __shared__ float Bs[64 * NC];
    __shared__ float As[ROWS * 64];
    const float* Bh = B + (size_t)blockIdx.y * K * NC;
    float* Ch = C + (size_t)blockIdx.y * NN * NC;
    int tid = threadIdx.x;
    int col = tid % NC, rl = tid / NC;
    int row0 = blockIdx.x * ROWS;
    float acc = 0.f;
    for (int kc = 0; kc < K; kc += 64) {
        for (int e = tid; e < 64 * NC; e += 256)
            Bs[e] = Bh[(size_t)(kc + e / NC) * NC + (e % NC)];
        for (int e = tid; e < ROWS * 64; e += 256)
            As[e] = A[(size_t)(row0 + e / 64) * K + kc + (e % 64)];
        __syncthreads();
        #pragma unroll 16
        for (int k = 0; k < 64; k++)
            acc += As[rl * 64 + k] * Bs[k * NC + col];
        __syncthreads();
    }
    Ch[(size_t)(row0 + rl) * NC + col] = acc;
}

// ---------------- f1/f2, head = blockIdx.y ----------------
__global__ void fvec(const float* __restrict__ h, const float* __restrict__ a,
                     int aStr, float* __restrict__ f1, float* __restrict__ f2) {
    size_t z = blockIdx.y;
    const float* hz = h + z * (size_t)NN * 64;
    const float* az = a + z * (size_t)aStr;
    int row = blockIdx.x * 8 + threadIdx.y;
    int lane = threadIdx.x;
    float v1 = 0.f, v2 = 0.f;
    #pragma unroll
    for (int d = lane; d < 64; d += 32) {
        float hv = hz[(size_t)row * 64 + d];
        v1 += hv * az[d];
        v2 += hv * az[64 + d];
    }
    #pragma unroll
    for (int o = 16; o; o >>= 1) {
        v1 += __shfl_down_sync(0xffffffffu, v1, o);
        v2 += __shfl_down_sync(0xffffffffu, v2, o);
    }
    if (lane == 0) { f1[z * NN + row] = v1; f2[z * NN + row] = v2; }
}

// ---------------- bitonic sort, warp-segment optimized; one block per head ----------------
__global__ void sortk(const float* __restrict__ f1, float* __restrict__ f1s,
                      int* __restrict__ piout) {
    __shared__ float k[NN];
    __shared__ int   id[NN];
    int tid = threadIdx.x;  // 1024
    size_t hz = blockIdx.x;
    const float* src = f1 + hz * NN;
    for (int r = tid; r < NN; r += 1024) { k[r] = src[r]; id[r] = r; }
    __syncthreads();
    int wlane = tid & 31;
    int segbase = (tid >> 5) * 128;
    for (int size = 2; size <= NN; size <<= 1) {
        int stride = size >> 1;
        for (; stride >= 128; stride >>= 1) {
            #pragma unroll
            for (int u = 0; u < 2; u++) {
                int t = u * 1024 + tid;
                int i = 2 * t - (t & (stride - 1));
                int j = i + stride;
                bool asc = ((i & size) == 0);
                float ki = k[i], kj = k[j];
                bool sw = asc ? (ki > kj) : (ki < kj);
                if (sw) {
                    k[i] = kj; k[j] = ki;
                    int ti = id[i]; id[i] = id[j]; id[j] = ti;
                }
            }
            __syncthreads();
        }
        for (; stride > 0; stride >>= 1) {
            #pragma unroll
            for (int u = 0; u < 2; u++) {
                int t = u * 32 + wlane;               // local pair idx 0..63
                int i = segbase + 2 * t - (t & (stride - 1));
                int j = i + stride;
                bool asc = ((i & size) == 0);
                float ki = k[i], kj = k[j];
                bool sw = asc ? (ki > kj) : (ki < kj);
                if (sw) {
                    k[i] = kj; k[j] = ki;
                    int ti = id[i]; id[i] = id[j]; id[j] = ti;
                }
            }
            __syncwarp();
        }
        __syncthreads();
    }
    float* dk = f1s + hz * NN;
    int* di = piout + hz * NN;
    for (int r = tid; r < NN; r += 1024) { dk[r] = k[r]; di[r] = id[r]; }
}

// ---------------- t_j, head = blockIdx.y ----------------
__global__ void tvec(const float* __restrict__ f1s, const float* __restrict__ f2,
                     int* __restrict__ tj) {
    size_t z = blockIdx.y;
    const float* fs = f1s + z * NN;
    int j = blockIdx.x * 256 + threadIdx.x;
    float thr = -f2[z * NN + j];
    int lo = 0, hi = NN;
    while (lo < hi) {
        int mid = (lo + hi) >> 1;
        if (fs[mid] <= thr) lo = mid + 1; else hi = mid;
    }
    tj[z * NN + j] = lo;
}

// ---------------- phase A: scans + softmax weights (bf16 pair), head = blockIdx.y ----------------
__global__ void phaseA(const float* __restrict__ adj, const int* __restrict__ pi,
                       const float* __restrict__ f1s, const float* __restrict__ f2,
                       const int* __restrict__ tj,
                       __nv_bfloat16* __restrict__ Whi, __nv_bfloat16* __restrict__ Wlo,
                       float* __restrict__ rinv) {
    extern __shared__ float sm[];
    float* arow = sm;
    float* sP = sm + 4096;
    float* sQ = sP + 4352;
    __shared__ float wsp[8], wsq[8];

    int i = blockIdx.x, tid = threadIdx.x;
    size_t hz = blockIdx.y;
    const int* piz = pi + hz * NN;
    const float* f1z = f1s + hz * NN;
    const float* f2z = f2 + hz * NN;
    const int* tjz = tj + hz * NN;

    const float* Arow = adj + (size_t)i * NN;
    for (int r = tid; r < NN; r += 256) arow[r] = Arow[r];
    __syncthreads();
    for (int r = tid; r < NN; r += 256) {
        float a = arow[piz[r]];
        int pr = ((r >> 4) * 17) + (r & 15);
        sP[pr] = a;
        sQ[pr] = a * f1z[r];
    }
    __syncthreads();
    int base = tid * 17;
    float p = 0.f, q = 0.f;
    #pragma unroll
    for (int u = 0; u < 16; u++) {
        p += sP[base + u]; sP[base + u] = p;
        q += sQ[base + u]; sQ[base + u] = q;
    }
    float ip = p, iq = q;
    unsigned lane = tid & 31, wid = tid >> 5;
    #pragma unroll
    for (int o = 1; o < 32; o <<= 1) {
        float tp = __shfl_up_sync(0xffffffffu, ip, o);
        float tq = __shfl_up_sync(0xffffffffu, iq, o);
        if (lane >= o) { ip += tp; iq += tq; }
    }
    if (lane == 31) { wsp[wid] = ip; wsq[wid] = iq; }
    __syncthreads();
    float offp = 0.f, offq = 0.f;
    for (int w = 0; w < 8; w++)
        if (w < (int)wid) { offp += wsp[w]; offq += wsq[w]; }
    float ep = offp + ip - p;
    float eq = offq + iq - q;
    #pragma unroll
    for (int u = 0; u < 16; u++) { sP[base + u] += ep; sQ[base + u] += eq; }
    __syncthreads();
    float A0 = sP[255 * 17 + 15];
    float A1 = sQ[255 * 17 + 15];

    float m = -3.0e38f;
    for (int j = tid; j < NN; j += 256) {
        float f2j = f2z[j];
        int t = tjz[j];
        float Pt = 0.f, Qt = 0.f;
        if (t > 0) {
            int pidx = (((t - 1) >> 4) * 17) + ((t - 1) & 15);
            Pt = sP[pidx]; Qt = sQ[pidx];
        }
        float S = A1 + A0 * f2j - OMA * (Qt + f2j * Pt);
        m = fmaxf(m, S);
    }
    #pragma unroll
    for (int o = 16; o; o >>= 1) m = fmaxf(m, __shfl_xor_sync(0xffffffffu, m, o));
    __syncthreads();
    if (lane == 0) wsp[wid] = m;
    __syncthreads();
    float mall = wsp[0];
    #pragma unroll
    for (int w = 1; w < 8; w++) mall = fmaxf(mall, wsp[w]);

    float z = 0.f;
    __nv_bfloat162* Wh = (__nv_bfloat162*)(Whi + hz * (size_t)NN * NN + (size_t)i * NN);
    __nv_bfloat162* Wl = (__nv_bfloat162*)(Wlo + hz * (size_t)NN * NN + (size_t)i * NN);
    for (int j0 = tid * 2; j0 < NN; j0 += 512) {
        float wv[2];
        #pragma unroll
        for (int u = 0; u < 2; u++) {
            int j = j0 + u;
            float f2j = f2z[j];
            int t = tjz[j];
            float Pt = 0.f, Qt = 0.f;
            if (t > 0) {
                int pidx = (((t - 1) >> 4) * 17) + ((t - 1) & 15);
                Pt = sP[pidx]; Qt = sQ[pidx];
            }
            float S = A1 + A0 * f2j - OMA * (Qt + f2j * Pt);
            wv[u] = __expf(S - mall);
            z += wv[u];
        }
        __nv_bfloat16 h0 = __float2bfloat16_rn(wv[0]);
        __nv_bfloat16 h1 = __float2bfloat16_rn(wv[1]);
        Wh[j0 >> 1] = __nv_bfloat162(h0, h1);
        Wl[j0 >> 1] = __nv_bfloat162(
            __float2bfloat16_rn(wv[0] - __bfloat162float(h0)),
            __float2bfloat16_rn(wv[1] - __bfloat162float(h1)));
    }
    #pragma unroll
    for (int o = 16; o; o >>= 1) z += __shfl_xor_sync(0xffffffffu, z, o);
    __syncthreads();
    if (lane == 0) wsq[wid] = z;
    __syncthreads();
    if (tid == 0) {
        float zt = 0.f;
        #pragma unroll
        for (int w = 0; w < 8; w++) zt += wsq[w];
        rinv[hz * NN + i] = 1.0f / zt;
    }
}

// ---------------- epilogue: combine split-K, scale, activation; head = blockIdx.y ----------------
__global__ void epilogue_k(const float* __restrict__ part, int splits,
                           const float* __restrict__ rinv, float* __restrict__ dst,
                           int ldc, int dstHeadOff, int mode) {
    size_t z = blockIdx.y;
    const float* pz = part + z * (size_t)splits * NN * 64;
    int idx = blockIdx.x * 256 + threadIdx.x;
    int row = idx >> 6, col = idx & 63;
    float v = 0.f;
    for (int s = 0; s < splits; s++) v += pz[(size_t)s * NN * 64 + idx];
    if (rinv) v *= rinv[z * NN + row];
    if (mode == 1) v = fmaxf(v, 0.f);
    else if (mode == 2) v = (v > 0.f) ? v : expm1f(v);
    dst[(size_t)row * ldc + z * dstHeadOff + col] = v;
}

__global__ void epi32(const float* __restrict__ part, float* __restrict__ dst) {
    int idx = blockIdx.x * 256 + threadIdx.x;
    int row = idx >> 5, col = idx & 31;
    float v = 0.f;
    for (int s = 0; s < 8; s++) v += part[(size_t)s * NN * 64 + (size_t)row * 64 + col];
    dst[idx] = v;
}

// ---------------- host orchestration ----------------
struct Bufs {
    __nv_bfloat16 *Whi, *Wlo, *ahi, *alo, *xhi, *xlo, *bhi, *blo;
    float *h, *cat, *x1, *tb, *h1, *u, *part, *f1, *f2, *f1s, *rinv;
    int *pi, *tj;
};

// single-head GAT (used for the out-attention layer)
static void run_gat_single(const float* adjc, const float* F, int Kf,
                           const float* Hm, const float* av,
                           float* dst, int ldc, const Bufs& b) {
    if (Kf == 64) mm_small<64, 64><<<NN / 4, 256>>>(F, Hm, b.h);
    else          mm_small<256, 64><<<NN / 4, 256>>>(F, Hm, b.h);
    fvec<<<dim3(NN / 8, 1), dim3(32, 8)>>>(b.h, av, 0, b.f1, b.f2);
    tconv<<<dim3(128, 2, 1), dim3(32, 8)>>>(b.h, 64, b.bhi, b.blo);
    sortk<<<1, 1024>>>(b.f1, b.f1s, b.pi);
    tvec<<<dim3(NN / 256, 1), 256>>>(b.f1s, b.f2, b.tj);
    phaseA<<<dim3(NN, 1), 256, (4096 + 4352 + 4352) * sizeof(float)>>>(
        adjc, b.pi, b.f1s, b.f2, b.tj, b.Whi, b.Wlo, b.rinv);
    mm_mma<<<dim3(32, 8, 1), 256, MMSMEM>>>(b.Whi, b.Wlo, b.bhi, b.blo, b.part, 0, 0);
    epilogue_k<<<dim3(NN * 64 / 256, 1), 256>>>(b.part, 8, b.rinv, dst, ldc, 0, 2);
}

// 4 heads batched -> writes cat [4096, 256] (elu applied)
static void run_heads(const float* adjc, const float* prev,
                      const float* HmBase, const float* avBase, const Bufs& b) {
    mm_small<64, 64><<<dim3(NN / 4, NH), 256>>>(prev, HmBase, b.h);
    fvec<<<dim3(NN / 8, NH), dim3(32, 8)>>>(b.h, avBase, 128, b.f1, b.f2);
    tconv<<<dim3(128, 2, NH), dim3(32, 8)>>>(b.h, 64, b.bhi, b.blo);
    sortk<<<NH, 1024>>>(b.f1, b.f1s, b.pi);
    tvec<<<dim3(NN / 256, NH), 256>>>(b.f1s, b.f2, b.tj);
    phaseA<<<dim3(NN, NH), 256, (4096 + 4352 + 4352) * sizeof(float)>>>(
        adjc, b.pi, b.f1s, b.f2, b.tj, b.Whi, b.Wlo, b.rinv);
    mm_mma<<<dim3(32, 2, NH), 256, MMSMEM>>>(b.Whi, b.Wlo, b.bhi, b.blo, b.part,
                                             (size_t)NN * NN, (size_t)64 * NN);
    epilogue_k<<<dim3(NN * 64 / 256, NH), 256>>>(b.part, 2, b.rinv, b.cat, 256, 64, 2);
}

extern "C" void kernel_launch(void* const* d_in, const int* in_sizes, int n_in,
                              void* d_out, int out_size) {
    const float* x      = (const float*)d_in[0];
    const float* adj    = (const float*)d_in[1];
    const float* w_init = (const float*)d_in[2];
    const float* head_H = (const float*)d_in[3];
    const float* head_a = (const float*)d_in[4];
    const float* out_H  = (const float*)d_in[5];
    const float* out_a  = (const float*)d_in[6];
    const float* l2_w   = (const float*)d_in[7];
    float* out = (float*)d_out;

    cudaFuncSetAttribute(phaseA, cudaFuncAttributeMaxDynamicSharedMemorySize,
                         (4096 + 4352 + 4352) * (int)sizeof(float));
    cudaFuncSetAttribute(mm_mma, cudaFuncAttributeMaxDynamicSharedMemorySize, MMSMEM);

    Bufs b;
    cudaGetSymbolAddress((void**)&b.Whi, g_Whi);
    cudaGetSymbolAddress((void**)&b.Wlo, g_Wlo);
    cudaGetSymbolAddress((void**)&b.ahi, g_ahi);
    cudaGetSymbolAddress((void**)&b.alo, g_alo);
    cudaGetSymbolAddress((void**)&b.xhi, g_xhi);
    cudaGetSymbolAddress((void**)&b.xlo, g_xlo);
    cudaGetSymbolAddress((void**)&b.bhi, g_bhi);
    cudaGetSymbolAddress((void**)&b.blo, g_blo);
    cudaGetSymbolAddress((void**)&b.h, g_h);
    cudaGetSymbolAddress((void**)&b.cat, g_cat);
    cudaGetSymbolAddress((void**)&b.x1, g_x1);
    cudaGetSymbolAddress((void**)&b.tb, g_tb);
    cudaGetSymbolAddress((void**)&b.h1, g_h1);
    cudaGetSymbolAddress((void**)&b.u, g_u);
    cudaGetSymbolAddress((void**)&b.part, g_part);
    cudaGetSymbolAddress((void**)&b.f1, g_f1);
    cudaGetSymbolAddress((void**)&b.f2, g_f2);
    cudaGetSymbolAddress((void**)&b.f1s, g_f1s);
    cudaGetSymbolAddress((void**)&b.rinv, g_rinv);
    cudaGetSymbolAddress((void**)&b.pi, g_pi);
    cudaGetSymbolAddress((void**)&b.tj, g_tj);

    const float* prev = w_init;
    for (int i = 0; i < 2; i++) {
        const float* adjc = adj + (size_t)i * NN * NN;
        run_heads(adjc, prev, head_H + (size_t)i * NH * 64 * 64,
                  head_a + (size_t)i * NH * 128, b);
        run_gat_single(adjc, b.cat, 256, out_H + (size_t)i * 256 * 64,
                       out_a + (size_t)i * 128, b.x1, 64, b);
        prev = b.x1;

        if (i == 1) {
            const float* xc = x + (size_t)i * NN * NN;
            cpair<<<4096, 256>>>((const float4*)xc, b.xhi, b.xlo);
            cpair<<<4096, 256>>>((const float4*)adjc, b.ahi, b.alo);
            // tb = x @ x1
            tconv<<<dim3(128, 2, 1), dim3(32, 8)>>>(b.x1, 64, b.bhi, b.blo);
            mm_mma<<<dim3(32, 8, 1), 256, MMSMEM>>>(b.xhi, b.xlo, b.bhi, b.blo, b.part, 0, 0);
            epilogue_k<<<dim3(NN * 64 / 256, 1), 256>>>(b.part, 8, nullptr, b.tb, 64, 0, 0);
            // h1 = relu(adj @ tb)
            tconv<<<dim3(128, 2, 1), dim3(32, 8)>>>(b.tb, 64, b.bhi, b.blo);
            mm_mma<<<dim3(32, 8, 1), 256, MMSMEM>>>(b.ahi, b.alo, b.bhi, b.blo, b.part, 0, 0);
            epilogue_k<<<dim3(NN * 64 / 256, 1), 256>>>(b.part, 8, nullptr, b.h1, 64, 0, 1);
            // u = h1 @ l2_w
            mm_small<64, 32><<<dim3(NN / 8, 1), 256>>>(b.h1, l2_w + (size_t)i * 64 * 32, b.u);
            // out = adj @ u (u zero-padded to 64 cols by tconv)
            tconv<<<dim3(128, 2, 1), dim3(32, 8)>>>(b.u, 32, b.bhi, b.blo);
            mm_mma<<<dim3(32, 8, 1), 256, MMSMEM>>>(b.ahi, b.alo, b.bhi, b.blo, b.part, 0, 0);
            epi32<<<NN * 32 / 256, 256>>>(b.part, out);
        }
    }
}

// round 6
// speedup vs baseline: 3.3207x; 1.3814x over previous
#include <cuda_runtime.h>
#include <cuda_bf16.h>
#include <math.h>
#include <stdint.h>

#define NN 4096
#define DD 64
#define OMA 0.8f   // 1 - alpha(0.2)
#define NH 4

// ---------------- scratch (device globals; allocation-free) ----------------
__device__ __nv_bfloat16 g_Whi[(size_t)NH * NN * NN];
__device__ __nv_bfloat16 g_Wlo[(size_t)NH * NN * NN];
__device__ __nv_bfloat16 g_ahi[(size_t)NN * NN];
__device__ __nv_bfloat16 g_alo[(size_t)NN * NN];
__device__ __nv_bfloat16 g_xhi[(size_t)NN * NN];
__device__ __nv_bfloat16 g_xlo[(size_t)NN * NN];
__device__ __nv_bfloat16 g_bhi[NH * 64 * NN];
__device__ __nv_bfloat16 g_blo[NH * 64 * NN];
__device__ float g_h[NH * NN * DD];
__device__ float g_cat[NN * NH * DD];
__device__ float g_x1[NN * DD];
__device__ float g_tb[NN * DD];
__device__ float g_h1[NN * DD];
__device__ float g_u[NN * 32];
__device__ float g_part[8 * NN * DD];
__device__ float g_f1[NH * NN], g_f2[NH * NN], g_f1s[NH * NN], g_rinv[NH * NN];
__device__ int   g_pi[NH * NN];
__device__ float2 g_pk[NH * NN];   // (f2_j, bitcast padded prefix index)

// ================= portable (sm_80+) PTX helpers =================
__device__ __forceinline__ uint32_t smem_u32(const void* p) {
    uint32_t a;
    asm("{ .reg .u64 t; cvta.to.shared.u64 t, %1; cvt.u32.u64 %0, t; }"
        : "=r"(a) : "l"(p));
    return a;
}

#define CP16(dst, src) \
    asm volatile("cp.async.cg.shared.global [%0], [%1], 16;" :: "r"(dst), "l"(src))
#define CP_COMMIT() asm volatile("cp.async.commit_group;" ::: "memory")
#define CP_WAIT0() asm volatile("cp.async.wait_group 0;" ::: "memory")
#define CP_WAIT1() asm volatile("cp.async.wait_group 1;" ::: "memory")

__device__ __forceinline__ void ldm4(uint32_t* r, uint32_t addr) {
    asm volatile("ldmatrix.sync.aligned.m8n8.x4.shared.b16 {%0,%1,%2,%3}, [%4];"
        : "=r"(r[0]), "=r"(r[1]), "=r"(r[2]), "=r"(r[3]) : "r"(addr));
}

__device__ __forceinline__ void mma16816(float* d, const uint32_t* a, const uint32_t* b) {
    asm volatile("mma.sync.aligned.m16n8k16.row.col.f32.bf16.bf16.f32 "
        "{%0,%1,%2,%3}, {%4,%5,%6,%7}, {%8,%9}, {%0,%1,%2,%3};"
        : "+f"(d[0]), "+f"(d[1]), "+f"(d[2]), "+f"(d[3])
        : "r"(a[0]), "r"(a[1]), "r"(a[2]), "r"(a[3]), "r"(b[0]), "r"(b[1]));
}

__device__ __forceinline__ uint32_t swz(uint32_t bo) { return bo ^ ((bo >> 3) & 0x70); }

// ================= tensor-core big matmul (mma.sync bf16 pair-split) =================
#define O_AH 0
#define O_AL 16384
#define O_BH 32768
#define O_BL 40960
#define STG  49152
#define MMSMEM (2 * STG)

__global__ void __launch_bounds__(256, 2) mm_mma(
        const __nv_bfloat16* __restrict__ Ahi, const __nv_bfloat16* __restrict__ Alo,
        const __nv_bfloat16* __restrict__ Bhi, const __nv_bfloat16* __restrict__ Blo,
        float* __restrict__ part, size_t aStr, size_t bStr) {
    extern __shared__ char smem[];
    uint32_t sb = smem_u32(smem);
    int tid = threadIdx.x, wid = tid >> 5, lane = tid & 31;
    int m0 = blockIdx.x * 128;
    int klen = NN / gridDim.y;
    int kbeg = blockIdx.y * klen;
    int nch = klen / 64;
    int wm = wid >> 1, wn = wid & 1;
    size_t zo = (size_t)blockIdx.z;
    const __nv_bfloat16* AhiZ = Ahi + zo * aStr;
    const __nv_bfloat16* AloZ = Alo + zo * aStr;
    const __nv_bfloat16* BhiZ = Bhi + zo * bStr;
    const __nv_bfloat16* BloZ = Blo + zo * bStr;

    auto load_chunk = [&](int ch) {
        uint32_t base = sb + (uint32_t)(ch & 1) * STG;
        int kc = kbeg + ch * 64;
        int r = tid >> 3, c = tid & 7;
        uint32_t sw = swz((uint32_t)(r * 128 + c * 16));
        #pragma unroll
        for (int pl = 0; pl < 2; pl++) {
            const __nv_bfloat16* src = pl ? AloZ : AhiZ;
            uint32_t off = pl ? O_AL : O_AH;
            #pragma unroll
            for (int i = 0; i < 4; i++)
                CP16(base + off + sw + (uint32_t)i * 4096,
                     src + (size_t)(m0 + r + i * 32) * NN + kc + c * 8);
        }
        #pragma unroll
        for (int pl = 0; pl < 2; pl++) {
            const __nv_bfloat16* src = pl ? BloZ : BhiZ;
            uint32_t off = pl ? O_BL : O_BH;
            #pragma unroll
            for (int i = 0; i < 2; i++)
                CP16(base + off + sw + (uint32_t)i * 4096,
                     src + (size_t)(r + i * 32) * NN + kc + c * 8);
        }
        CP_COMMIT();
    };

    float acc[2][4][4] = {};
    load_chunk(0);
    for (int ch = 0; ch < nch; ch++) {
        if (ch + 1 < nch) { load_chunk(ch + 1); CP_WAIT1(); }
        else               { CP_WAIT0(); }
        __syncthreads();
        uint32_t base = sb + (uint32_t)(ch & 1) * STG;
        #pragma unroll
        for (int ks = 0; ks < 4; ks++) {
            uint32_t ah[2][4], al[2][4], bh[8], bl[8];
            #pragma unroll
            for (int mt = 0; mt < 2; mt++) {
                int row = wm * 32 + mt * 16 + (lane & 7) + ((lane >> 3) & 1) * 8;
                int koff = ks * 32 + (lane >> 4) * 16;
                uint32_t sw = swz((uint32_t)(row * 128 + koff));
                ldm4(ah[mt], base + O_AH + sw);
                ldm4(al[mt], base + O_AL + sw);
            }
            #pragma unroll
            for (int half = 0; half < 2; half++) {
                int g = lane >> 3;
                int n = wn * 32 + half * 16 + (g >> 1) * 8 + (lane & 7);
                int koff = ks * 32 + (g & 1) * 16;
                uint32_t sw = swz((uint32_t)(n * 128 + koff));
                ldm4(bh + half * 4, base + O_BH + sw);
                ldm4(bl + half * 4, base + O_BL + sw);
            }
            #pragma unroll
            for (int mt = 0; mt < 2; mt++)
                #pragma unroll
                for (int nt = 0; nt < 4; nt++) {
                    mma16816(acc[mt][nt], ah[mt], bh + nt * 2);
                    mma16816(acc[mt][nt], ah[mt], bl + nt * 2);
                    mma16816(acc[mt][nt], al[mt], bh + nt * 2);
                }
        }
        __syncthreads();
    }

    float* cp = part + ((size_t)blockIdx.z * gridDim.y + blockIdx.y) * (NN * 64);
    #pragma unroll
    for (int mt = 0; mt < 2; mt++)
        #pragma unroll
        for (int nt = 0; nt < 4; nt++) {
            int row = m0 + wm * 32 + mt * 16 + (lane >> 2);
            int col = wn * 32 + nt * 8 + (lane & 3) * 2;
            *(float2*)&cp[(size_t)row * 64 + col] =
                make_float2(acc[mt][nt][0], acc[mt][nt][1]);
            *(float2*)&cp[(size_t)(row + 8) * 64 + col] =
                make_float2(acc[mt][nt][2], acc[mt][nt][3]);
        }
}

// ---------------- fp32 -> bf16 pair planes (big matrices) ----------------
__global__ void cpair(const float4* __restrict__ in, __nv_bfloat16* __restrict__ hi,
                      __nv_bfloat16* __restrict__ lo) {
    size_t n4 = (size_t)NN * NN / 4;
    for (size_t i = (size_t)blockIdx.x * 256 + threadIdx.x; i < n4;
         i += (size_t)gridDim.x * 256) {
        float4 v = in[i];
        __nv_bfloat16 h0 = __float2bfloat16_rn(v.x);
        __nv_bfloat16 h1 = __float2bfloat16_rn(v.y);
        __nv_bfloat16 h2 = __float2bfloat16_rn(v.z);
        __nv_bfloat16 h3 = __float2bfloat16_rn(v.w);
        __nv_bfloat162* H = (__nv_bfloat162*)hi;
        __nv_bfloat162* L = (__nv_bfloat162*)lo;
        H[2 * i]     = __nv_bfloat162(h0, h1);
        H[2 * i + 1] = __nv_bfloat162(h2, h3);
        L[2 * i]     = __nv_bfloat162(__float2bfloat16_rn(v.x - __bfloat162float(h0)),
                                      __float2bfloat16_rn(v.y - __bfloat162float(h1)));
        L[2 * i + 1] = __nv_bfloat162(__float2bfloat16_rn(v.z - __bfloat162float(h2)),
                                      __float2bfloat16_rn(v.w - __bfloat162float(h3)));
    }
}

// ---------------- transpose+convert ----------------
__global__ void tconv(const float* __restrict__ in, int C,
                      __nv_bfloat16* __restrict__ ohi, __nv_bfloat16* __restrict__ olo) {
    __shared__ float t[32][33];
    size_t z = blockIdx.z;
    const float* inz = in + z * (size_t)NN * 64;
    __nv_bfloat16* oh = ohi + z * (size_t)64 * NN;
    __nv_bfloat16* ol = olo + z * (size_t)64 * NN;
    int bx = blockIdx.x, by = blockIdx.y;
    int x = threadIdx.x, y = threadIdx.y;   // 32x8
    int col0 = by * 32;
    for (int yy = y; yy < 32; yy += 8) {
        int r = bx * 32 + yy, c = col0 + x;
        t[yy][x] = (c < C) ? inz[(size_t)r * C + c] : 0.f;
    }
    __syncthreads();
    for (int yy = y; yy < 32; yy += 8) {
        int n = col0 + yy;
        int k = bx * 32 + x;
        float v = t[x][yy];
        __nv_bfloat16 h = __float2bfloat16_rn(v);
        oh[(size_t)n * NN + k] = h;
        ol[(size_t)n * NN + k] = __float2bfloat16_rn(v - __bfloat162float(h));
    }
}

// ---------------- small matmul ----------------
template<int K, int NC>
__global__ void mm_small(const float* __restrict__ A, const float* __restrict__ B,
                         float* __restrict__ C) {
    constexpr int ROWS = 256 / NC;
    __shared__ float Bs[64 * NC];
    __shared__ float As[ROWS * 64];
    const float* Bh = B + (size_t)blockIdx.y * K * NC;
    float* Ch = C + (size_t)blockIdx.y * NN * NC;
    int tid = threadIdx.x;
    int col = tid % NC, rl = tid / NC;
    int row0 = blockIdx.x * ROWS;
    float acc = 0.f;
    for (int kc = 0; kc < K; kc += 64) {
        for (int e = tid; e < 64 * NC; e += 256)
            Bs[e] = Bh[(size_t)(kc + e / NC) * NC + (e % NC)];
        for (int e = tid; e < ROWS * 64; e += 256)
            As[e] = A[(size_t)(row0 + e / 64) * K + kc + (e % 64)];
        __syncthreads();
        #pragma unroll 16
        for (int k = 0; k < 64; k++)
            acc += As[rl * 64 + k] * Bs[k * NC + col];
        __syncthreads();
    }
    Ch[(size_t)(row0 + rl) * NC + col] = acc;
}

// ---------------- f1/f2 ----------------
__global__ void fvec(const float* __restrict__ h, const float* __restrict__ a,
                     int aStr, float* __restrict__ f1, float* __restrict__ f2) {
    size_t z = blockIdx.y;
    const float* hz = h + z * (size_t)NN * 64;
    const float* az = a + z * (size_t)aStr;
    int row = blockIdx.x * 8 + threadIdx.y;
    int lane = threadIdx.x;
    float v1 = 0.f, v2 = 0.f;
    #pragma unroll
    for (int d = lane; d < 64; d += 32) {
        float hv = hz[(size_t)row * 64 + d];
        v1 += hv * az[d];
        v2 += hv * az[64 + d];
    }
    #pragma unroll
    for (int o = 16; o; o >>= 1) {
        v1 += __shfl_down_sync(0xffffffffu, v1, o);
        v2 += __shfl_down_sync(0xffffffffu, v2, o);
    }
    if (lane == 0) { f1[z * NN + row] = v1; f2[z * NN + row] = v2; }
}

// ---------------- block radix sort (4x8-bit LSD, stable), one block per head ----------------
// dyn smem layout: keyA(16K) keyB(16K) valA(8K) valB(8K) cnt u16[4][32][256](64K) hist(1K) base(1K)
#define RDXS (16384 + 16384 + 8192 + 8192 + 65536 + 1024 + 1024)

__global__ void __launch_bounds__(1024, 1) sortk(
        const float* __restrict__ f1, float* __restrict__ f1s, int* __restrict__ piout) {
    extern __shared__ char rs[];
    uint32_t* keyA = (uint32_t*)rs;
    uint32_t* keyB = (uint32_t*)(rs + 16384);
    uint16_t* valA = (uint16_t*)(rs + 32768);
    uint16_t* valB = (uint16_t*)(rs + 40960);
    uint16_t* cnt  = (uint16_t*)(rs + 49152);                 // [4][32][256]
    uint32_t* hist = (uint32_t*)(rs + 49152 + 65536);
    uint32_t* base = hist + 256;

    int tid = threadIdx.x;  // 1024
    int lane = tid & 31, wid = tid >> 5;
    size_t hz = blockIdx.x;
    const float* src = f1 + hz * NN;

    for (int i = tid; i < NN; i += 1024) {
        uint32_t b = __float_as_uint(src[i]);
        keyA[i] = b ^ ((b & 0x80000000u) ? 0xFFFFFFFFu : 0x80000000u);
        valA[i] = (uint16_t)i;
    }
    __syncthreads();

    uint32_t* KA = keyA; uint32_t* KB = keyB;
    uint16_t* VA = valA; uint16_t* VB = valB;

    for (int shift = 0; shift < 32; shift += 8) {
        uint32_t k[4], d[4]; uint16_t v[4];
        #pragma unroll
        for (int s = 0; s < 4; s++) {
            k[s] = KA[s * 1024 + tid];
            v[s] = VA[s * 1024 + tid];
            d[s] = (k[s] >> shift) & 255u;
        }
        // zero counts (64KB = 16K u32)
        uint32_t* cz = (uint32_t*)cnt;
        #pragma unroll
        for (int i = 0; i < 16; i++) cz[i * 1024 + tid] = 0;
        __syncthreads();
        // per (slot, warp, digit) counts — one writer per group leader
        #pragma unroll
        for (int s = 0; s < 4; s++) {
            uint32_t mask = __match_any_sync(0xffffffffu, d[s]);
            if ((mask & ((1u << lane) - 1)) == 0)
                cnt[(s * 32 + wid) * 256 + d[s]] = (uint16_t)__popc(mask);
        }
        __syncthreads();
        // serial prefix over 128 (s,w) per digit + totals
        if (tid < 256) {
            uint32_t run = 0;
            for (int sw = 0; sw < 128; sw++) {
                uint32_t c = cnt[sw * 256 + tid];
                cnt[sw * 256 + tid] = (uint16_t)run;
                run += c;
            }
            hist[tid] = run;
            base[tid] = run;
        }
        __syncthreads();
        // inclusive scan over 256 digits
        for (int o = 1; o < 256; o <<= 1) {
            uint32_t x = 0;
            if (tid < 256 && tid >= (uint32_t)o) x = base[tid - o];
            __syncthreads();
            if (tid < 256) base[tid] += x;
            __syncthreads();
        }
        // scatter
        #pragma unroll
        for (int s = 0; s < 4; s++) {
            uint32_t mask = __match_any_sync(0xffffffffu, d[s]);
            uint32_t rank = __popc(mask & ((1u << lane) - 1));
            uint32_t db = d[s] ? base[d[s] - 1] : 0u;
            uint32_t pos = db + (uint32_t)cnt[(s * 32 + wid) * 256 + d[s]] + rank;
            KB[pos] = k[s];
            VB[pos] = v[s];
        }
        __syncthreads();
        uint32_t* tk = KA; KA = KB; KB = tk;
        uint16_t* tv = VA; VA = VB; VB = tv;
    }
    // 4 passes -> results back in A buffers
    float* dk = f1s + hz * NN;
    int* di = piout + hz * NN;
    for (int i = tid; i < NN; i += 1024) {
        uint32_t u = KA[i];
        uint32_t b = (u & 0x80000000u) ? (u ^ 0x80000000u) : ~u;
        dk[i] = __uint_as_float(b);
        di[i] = (int)VA[i];
    }
}

// ---------------- tvec: pack (f2_j, padded prefix idx) ----------------
__global__ void tvec(const float* __restrict__ f1s, const float* __restrict__ f2,
                     float2* __restrict__ pk) {
    size_t z = blockIdx.y;
    const float* fs = f1s + z * NN;
    int j = blockIdx.x * 256 + threadIdx.x;
    float f2j = f2[z * NN + j];
    float thr = -f2j;
    int lo = 0, hi = NN;
    while (lo < hi) {
        int mid = (lo + hi) >> 1;
        if (fs[mid] <= thr) lo = mid + 1; else hi = mid;
    }
    int pidx = 16;   // slot 16 is a guaranteed-zero pad slot
    if (lo > 0) pidx = ((lo - 1) >> 4) * 17 + ((lo - 1) & 15);
    pk[z * NN + j] = make_float2(f2j, __int_as_float(pidx));
}

// ---------------- phase A: all heads per block, S cached in smem ----------------
// dyn smem: arow[4096] sP[4352] sQ[4352] sS[4096]  = 16896 floats
#define PASMEM (16896 * 4)

__global__ void phaseA(const float* __restrict__ adj, const int* __restrict__ pi,
                       const float* __restrict__ f1s, const float2* __restrict__ pk,
                       __nv_bfloat16* __restrict__ Whi, __nv_bfloat16* __restrict__ Wlo,
                       float* __restrict__ rinv, int nheads) {
    extern __shared__ float sm[];
    float* arow = sm;             // 4096
    float* sP = sm + 4096;        // 4352
    float* sQ = sP + 4352;        // 4352
    float* sS = sQ + 4352;        // 4096
    __shared__ float wsp[8], wsq[8];

    int i = blockIdx.x, tid = threadIdx.x;
    unsigned lane = tid & 31, wid = tid >> 5;

    const float* Arow = adj + (size_t)i * NN;
    for (int r = tid; r < NN; r += 256) arow[r] = Arow[r];
    if (tid == 0) { sP[16] = 0.f; sQ[16] = 0.f; }
    __syncthreads();

    for (int hz = 0; hz < nheads; hz++) {
        const int* piz = pi + (size_t)hz * NN;
        const float* f1z = f1s + (size_t)hz * NN;
        const float2* pkz = pk + (size_t)hz * NN;

        for (int r = tid; r < NN; r += 256) {
            float a = arow[piz[r]];
            int pr = ((r >> 4) * 17) + (r & 15);
            sP[pr] = a;
            sQ[pr] = a * f1z[r];
        }
        __syncthreads();
        int base = tid * 17;
        float p = 0.f, q = 0.f;
        #pragma unroll
        for (int u = 0; u < 16; u++) {
            p += sP[base + u]; sP[base + u] = p;
            q += sQ[base + u]; sQ[base + u] = q;
        }
        float ip = p, iq = q;
        #pragma unroll
        for (int o = 1; o < 32; o <<= 1) {
            float tp = __shfl_up_sync(0xffffffffu, ip, o);
            float tq = __shfl_up_sync(0xffffffffu, iq, o);
            if (lane >= o) { ip += tp; iq += tq; }
        }
        if (lane == 31) { wsp[wid] = ip; wsq[wid] = iq; }
        __syncthreads();
        float offp = 0.f, offq = 0.f;
        for (int w = 0; w < 8; w++)
            if (w < (int)wid) { offp += wsp[w]; offq += wsq[w]; }
        float ep = offp + ip - p;
        float eq = offq + iq - q;
        #pragma unroll
        for (int u = 0; u < 16; u++) { sP[base + u] += ep; sQ[base + u] += eq; }
        __syncthreads();
        float A0 = sP[255 * 17 + 15];
        float A1 = sQ[255 * 17 + 15];

        // pass 1: S into smem + row max
        float m = -3.0e38f;
        for (int j = tid; j < NN; j += 256) {
            float2 pj = pkz[j];
            float f2j = pj.x;
            int pidx = __float_as_int(pj.y);
            float S = A1 + A0 * f2j - OMA * (sQ[pidx] + f2j * sP[pidx]);
            sS[j] = S;
            m = fmaxf(m, S);
        }
        #pragma unroll
        for (int o = 16; o; o >>= 1) m = fmaxf(m, __shfl_xor_sync(0xffffffffu, m, o));
        __syncthreads();
        if (lane == 0) wsp[wid] = m;
        __syncthreads();
        float mall = wsp[0];
        #pragma unroll
        for (int w = 1; w < 8; w++) mall = fmaxf(mall, wsp[w]);

        // pass 2: exp from smem, sum, write bf16 pair
        float z = 0.f;
        __nv_bfloat162* Wh = (__nv_bfloat162*)(Whi + (size_t)hz * NN * NN + (size_t)i * NN);
        __nv_bfloat162* Wl = (__nv_bfloat162*)(Wlo + (size_t)hz * NN * NN + (size_t)i * NN);
        for (int j0 = tid * 2; j0 < NN; j0 += 512) {
            float w0 = __expf(sS[j0] - mall);
            float w1 = __expf(sS[j0 + 1] - mall);
            z += w0 + w1;
            __nv_bfloat16 h0 = __float2bfloat16_rn(w0);
            __nv_bfloat16 h1 = __float2bfloat16_rn(w1);
            Wh[j0 >> 1] = __nv_bfloat162(h0, h1);
            Wl[j0 >> 1] = __nv_bfloat162(
                __float2bfloat16_rn(w0 - __bfloat162float(h0)),
                __float2bfloat16_rn(w1 - __bfloat162float(h1)));
        }
        #pragma unroll
        for (int o = 16; o; o >>= 1) z += __shfl_xor_sync(0xffffffffu, z, o);
        __syncthreads();
        if (lane == 0) wsq[wid] = z;
        __syncthreads();
        if (tid == 0) {
            float zt = 0.f;
            #pragma unroll
            for (int w = 0; w < 8; w++) zt += wsq[w];
            rinv[(size_t)hz * NN + i] = 1.0f / zt;
        }
        __syncthreads();
    }
}

// ---------------- epilogues ----------------
__global__ void epilogue_k(const float* __restrict__ part, int splits,
                           const float* __restrict__ rinv, float* __restrict__ dst,
                           int ldc, int dstHeadOff, int mode) {
    size_t z = blockIdx.y;
    const float* pz = part + z * (size_t)splits * NN * 64;
    int idx = blockIdx.x * 256 + threadIdx.x;
    int row = idx >> 6, col = idx & 63;
    float v = 0.f;
    for (int s = 0; s < splits; s++) v += pz[(size_t)s * NN * 64 + idx];
    if (rinv) v *= rinv[z * NN + row];
    if (mode == 1) v = fmaxf(v, 0.f);
    else if (mode == 2) v = (v > 0.f) ? v : expm1f(v);
    dst[(size_t)row * ldc + z * dstHeadOff + col] = v;
}

__global__ void epi32(const float* __restrict__ part, float* __restrict__ dst) {
    int idx = blockIdx.x * 256 + threadIdx.x;
    int row = idx >> 5, col = idx & 31;
    float v = 0.f;
    for (int s = 0; s < 8; s++) v += part[(size_t)s * NN * 64 + (size_t)row * 64 + col];
    dst[idx] = v;
}

// ---------------- host orchestration ----------------
struct Bufs {
    __nv_bfloat16 *Whi, *Wlo, *ahi, *alo, *xhi, *xlo, *bhi, *blo;
    float *h, *cat, *x1, *tb, *h1, *u, *part, *f1, *f2, *f1s, *rinv;
    int *pi;
    float2 *pk;
};

static void run_gat_single(const float* adjc, const float* F, int Kf,
                           const float* Hm, const float* av,
                           float* dst, int ldc, const Bufs& b) {
    if (Kf == 64) mm_small<64, 64><<<NN / 4, 256>>>(F, Hm, b.h);
    else          mm_small<256, 64><<<NN / 4, 256>>>(F, Hm, b.h);
    fvec<<<dim3(NN / 8, 1), dim3(32, 8)>>>(b.h, av, 0, b.f1, b.f2);
    tconv<<<dim3(128, 2, 1), dim3(32, 8)>>>(b.h, 64, b.bhi, b.blo);
    sortk<<<1, 1024, RDXS>>>(b.f1, b.f1s, b.pi);
    tvec<<<dim3(NN / 256, 1), 256>>>(b.f1s, b.f2, b.pk);
    phaseA<<<NN, 256, PASMEM>>>(adjc, b.pi, b.f1s, b.pk, b.Whi, b.Wlo, b.rinv, 1);
    mm_mma<<<dim3(32, 8, 1), 256, MMSMEM>>>(b.Whi, b.Wlo, b.bhi, b.blo, b.part, 0, 0);
    epilogue_k<<<dim3(NN * 64 / 256, 1), 256>>>(b.part, 8, b.rinv, dst, ldc, 0, 2);
}

static void run_heads(const float* adjc, const float* prev,
                      const float* HmBase, const float* avBase, const Bufs& b) {
    mm_small<64, 64><<<dim3(NN / 4, NH), 256>>>(prev, HmBase, b.h);
    fvec<<<dim3(NN / 8, NH), dim3(32, 8)>>>(b.h, avBase, 128, b.f1, b.f2);
    tconv<<<dim3(128, 2, NH), dim3(32, 8)>>>(b.h, 64, b.bhi, b.blo);
    sortk<<<NH, 1024, RDXS>>>(b.f1, b.f1s, b.pi);
    tvec<<<dim3(NN / 256, NH), 256>>>(b.f1s, b.f2, b.pk);
    phaseA<<<NN, 256, PASMEM>>>(adjc, b.pi, b.f1s, b.pk, b.Whi, b.Wlo, b.rinv, NH);
    mm_mma<<<dim3(32, 2, NH), 256, MMSMEM>>>(b.Whi, b.Wlo, b.bhi, b.blo, b.part,
                                             (size_t)NN * NN, (size_t)64 * NN);
    epilogue_k<<<dim3(NN * 64 / 256, NH), 256>>>(b.part, 2, b.rinv, b.cat, 256, 64, 2);
}

extern "C" void kernel_launch(void* const* d_in, const int* in_sizes, int n_in,
                              void* d_out, int out_size) {
    const float* x      = (const float*)d_in[0];
    const float* adj    = (const float*)d_in[1];
    const float* w_init = (const float*)d_in[2];
    const float* head_H = (const float*)d_in[3];
    const float* head_a = (const float*)d_in[4];
    const float* out_H  = (const float*)d_in[5];
    const float* out_a  = (const float*)d_in[6];
    const float* l2_w   = (const float*)d_in[7];
    float* out = (float*)d_out;

    cudaFuncSetAttribute(phaseA, cudaFuncAttributeMaxDynamicSharedMemorySize, PASMEM);
    cudaFuncSetAttribute(mm_mma, cudaFuncAttributeMaxDynamicSharedMemorySize, MMSMEM);
    cudaFuncSetAttribute(sortk, cudaFuncAttributeMaxDynamicSharedMemorySize, RDXS);

    Bufs b;
    cudaGetSymbolAddress((void**)&b.Whi, g_Whi);
    cudaGetSymbolAddress((void**)&b.Wlo, g_Wlo);
    cudaGetSymbolAddress((void**)&b.ahi, g_ahi);
    cudaGetSymbolAddress((void**)&b.alo, g_alo);
    cudaGetSymbolAddress((void**)&b.xhi, g_xhi);
    cudaGetSymbolAddress((void**)&b.xlo, g_xlo);
    cudaGetSymbolAddress((void**)&b.bhi, g_bhi);
    cudaGetSymbolAddress((void**)&b.blo, g_blo);
    cudaGetSymbolAddress((void**)&b.h, g_h);
    cudaGetSymbolAddress((void**)&b.cat, g_cat);
    cudaGetSymbolAddress((void**)&b.x1, g_x1);
    cudaGetSymbolAddress((void**)&b.tb, g_tb);
    cudaGetSymbolAddress((void**)&b.h1, g_h1);
    cudaGetSymbolAddress((void**)&b.u, g_u);
    cudaGetSymbolAddress((void**)&b.part, g_part);
    cudaGetSymbolAddress((void**)&b.f1, g_f1);
    cudaGetSymbolAddress((void**)&b.f2, g_f2);
    cudaGetSymbolAddress((void**)&b.f1s, g_f1s);
    cudaGetSymbolAddress((void**)&b.rinv, g_rinv);
    cudaGetSymbolAddress((void**)&b.pi, g_pi);
    cudaGetSymbolAddress((void**)&b.pk, g_pk);

    const float* prev = w_init;
    for (int i = 0; i < 2; i++) {
        const float* adjc = adj + (size_t)i * NN * NN;
        run_heads(adjc, prev, head_H + (size_t)i * NH * 64 * 64,
                  head_a + (size_t)i * NH * 128, b);
        run_gat_single(adjc, b.cat, 256, out_H + (size_t)i * 256 * 64,
                       out_a + (size_t)i * 128, b.x1, 64, b);
        prev = b.x1;

        if (i == 1) {
            const float* xc = x + (size_t)i * NN * NN;
            cpair<<<4096, 256>>>((const float4*)xc, b.xhi, b.xlo);
            cpair<<<4096, 256>>>((const float4*)adjc, b.ahi, b.alo);
            // tb = x @ x1
            tconv<<<dim3(128, 2, 1), dim3(32, 8)>>>(b.x1, 64, b.bhi, b.blo);
            mm_mma<<<dim3(32, 8, 1), 256, MMSMEM>>>(b.xhi, b.xlo, b.bhi, b.blo, b.part, 0, 0);
            epilogue_k<<<dim3(NN * 64 / 256, 1), 256>>>(b.part, 8, nullptr, b.tb, 64, 0, 0);
            // h1 = relu(adj @ tb)
            tconv<<<dim3(128, 2, 1), dim3(32, 8)>>>(b.tb, 64, b.bhi, b.blo);
            mm_mma<<<dim3(32, 8, 1), 256, MMSMEM>>>(b.ahi, b.alo, b.bhi, b.blo, b.part, 0, 0);
            epilogue_k<<<dim3(NN * 64 / 256, 1), 256>>>(b.part, 8, nullptr, b.h1, 64, 0, 1);
            // u = h1 @ l2_w
            mm_small<64, 32><<<dim3(NN / 8, 1), 256>>>(b.h1, l2_w + (size_t)i * 64 * 32, b.u);
            // out = adj @ u (u zero-padded to 64 cols by tconv)
            tconv<<<dim3(128, 2, 1), dim3(32, 8)>>>(b.u, 32, b.bhi, b.blo);
            mm_mma<<<dim3(32, 8, 1), 256, MMSMEM>>>(b.ahi, b.alo, b.bhi, b.blo, b.part, 0, 0);
            epi32<<<NN * 32 / 256, 256>>>(b.part, out);
        }
    }
}